// round 8
// baseline (speedup 1.0000x reference)
#include <cuda_runtime.h>
#include <cuda_bf16.h>
#include <math.h>
#include <stdint.h>

#define BATCH  4
#define SEQ    1024
#define DMODEL 1024
#define NHEAD  16
#define DHEAD  64
#define NTOK   (BATCH * SEQ)

// ---------------- scratch (device globals; no runtime alloc) ----------------
__device__ __nv_bfloat16 g_qh[NTOK * DMODEL], g_ql[NTOK * DMODEL];
__device__ __nv_bfloat16 g_kh[NTOK * DMODEL], g_kl[NTOK * DMODEL];
__device__ __nv_bfloat16 g_vh[NTOK * DMODEL], g_vl[NTOK * DMODEL];
__device__ __nv_bfloat16 g_wqh[DMODEL * DMODEL], g_wql[DMODEL * DMODEL];
__device__ __nv_bfloat16 g_wkh[DMODEL * DMODEL], g_wkl[DMODEL * DMODEL];
__device__ __nv_bfloat16 g_wvh[DMODEL * DMODEL], g_wvl[DMODEL * DMODEL];
__device__ __nv_bfloat16 g_woh[DMODEL * DMODEL], g_wol[DMODEL * DMODEL];
// projected Q/K/V hi/lo in [b,h,s,64] layout  (Q pre-scaled by 0.125*log2e)
__device__ __nv_bfloat16 g_oqh[NTOK * DMODEL], g_oql[NTOK * DMODEL];
__device__ __nv_bfloat16 g_okh[NTOK * DMODEL], g_okl[NTOK * DMODEL];
__device__ __nv_bfloat16 g_ovh[NTOK * DMODEL], g_ovl[NTOK * DMODEL];
// attention context hi/lo, row-major [tok][1024]
__device__ __nv_bfloat16 g_ch[NTOK * DMODEL], g_cl[NTOK * DMODEL];
// fused mask*group: allowed ? group : -1
__device__ float g_gm[BATCH * SEQ * SEQ];

// ---------------------------------------------------------------------------
// shared PTX helpers
// ---------------------------------------------------------------------------
__device__ __forceinline__ uint32_t s2u(const void* p) {
    uint32_t a;
    asm("{ .reg .u64 t; cvta.to.shared.u64 t, %1; cvt.u32.u64 %0, t; }"
        : "=r"(a) : "l"(p));
    return a;
}
__device__ __forceinline__ void cp16(uint32_t dst, const void* src) {
    asm volatile("cp.async.cg.shared.global [%0], [%1], 16;" :: "r"(dst), "l"(src));
}
__device__ __forceinline__ void ldm_x4(uint32_t* r, uint32_t addr) {
    asm volatile("ldmatrix.sync.aligned.m8n8.x4.shared.b16 {%0,%1,%2,%3}, [%4];"
                 : "=r"(r[0]), "=r"(r[1]), "=r"(r[2]), "=r"(r[3]) : "r"(addr));
}
__device__ __forceinline__ void ldm_x4_t(uint32_t* r, uint32_t addr) {
    asm volatile("ldmatrix.sync.aligned.m8n8.x4.trans.shared.b16 {%0,%1,%2,%3}, [%4];"
                 : "=r"(r[0]), "=r"(r[1]), "=r"(r[2]), "=r"(r[3]) : "r"(addr));
}
__device__ __forceinline__ void mma_bf16(float* c, const uint32_t* a,
                                         const uint32_t* b) {
    asm volatile(
        "mma.sync.aligned.m16n8k16.row.col.f32.bf16.bf16.f32 "
        "{%0,%1,%2,%3}, {%4,%5,%6,%7}, {%8,%9}, {%0,%1,%2,%3};"
        : "+f"(c[0]), "+f"(c[1]), "+f"(c[2]), "+f"(c[3])
        : "r"(a[0]), "r"(a[1]), "r"(a[2]), "r"(a[3]), "r"(b[0]), "r"(b[1]));
}
__device__ __forceinline__ uint32_t swz(uint32_t byte) {
    return byte ^ ((byte >> 3) & 0x70);
}
__device__ __forceinline__ void split2(float x, float y, uint32_t& hi, uint32_t& lo) {
    asm("cvt.rn.bf16x2.f32 %0, %1, %2;" : "=r"(hi) : "f"(y), "f"(x));
    const float xr = x - __uint_as_float(hi << 16);
    const float yr = y - __uint_as_float(hi & 0xffff0000u);
    asm("cvt.rn.bf16x2.f32 %0, %1, %2;" : "=r"(lo) : "f"(yr), "f"(xr));
}
__device__ __forceinline__ float ex2(float x) {
    float r;
    asm("ex2.approx.f32 %0, %1;" : "=f"(r) : "f"(x));
    return r;
}

// ---------------------------------------------------------------------------
// conversions (merged launches)
// ---------------------------------------------------------------------------
__device__ __forceinline__ void cvt_body(const float* __restrict__ src,
                                         __nv_bfloat16* __restrict__ hi,
                                         __nv_bfloat16* __restrict__ lo, int t)
{
    const int idx = t * 8;
    const float4 a = *(const float4*)(src + idx);
    const float4 b = *(const float4*)(src + idx + 4);
    const float f[8] = {a.x, a.y, a.z, a.w, b.x, b.y, b.z, b.w};
    union { __nv_bfloat16 h[8]; uint4 u; } ph, pl;
#pragma unroll
    for (int i = 0; i < 8; i++) {
        const __nv_bfloat16 hh = __float2bfloat16(f[i]);
        ph.h[i] = hh;
        pl.h[i] = __float2bfloat16(f[i] - __bfloat162float(hh));
    }
    *(uint4*)(hi + idx) = ph.u;
    *(uint4*)(lo + idx) = pl.u;
}

__global__ __launch_bounds__(256) void cvt_act_kernel(
    const float* __restrict__ s0, const float* __restrict__ s1,
    const float* __restrict__ s2)
{
    const int t = blockIdx.x * 256 + threadIdx.x;
    if (t >= NTOK * (DMODEL / 8)) return;
    const int z = blockIdx.y;
    const float* src = (z == 0) ? s0 : (z == 1) ? s1 : s2;
    __nv_bfloat16* hi = (z == 0) ? g_qh : (z == 1) ? g_kh : g_vh;
    __nv_bfloat16* lo = (z == 0) ? g_ql : (z == 1) ? g_kl : g_vl;
    cvt_body(src, hi, lo, t);
}

__global__ __launch_bounds__(256) void cvt_w_kernel(
    const float* __restrict__ s0, const float* __restrict__ s1,
    const float* __restrict__ s2, const float* __restrict__ s3)
{
    const int t = blockIdx.x * 256 + threadIdx.x;
    if (t >= DMODEL * (DMODEL / 8)) return;
    const int z = blockIdx.y;
    const float* src = (z == 0) ? s0 : (z == 1) ? s1 : (z == 2) ? s2 : s3;
    __nv_bfloat16* hi = (z == 0) ? g_wqh : (z == 1) ? g_wkh : (z == 2) ? g_wvh : g_woh;
    __nv_bfloat16* lo = (z == 0) ? g_wql : (z == 1) ? g_wkl : (z == 2) ? g_wvl : g_wol;
    cvt_body(src, hi, lo, t);
}

__global__ __launch_bounds__(256) void prep_gm_kernel(
    const int* __restrict__ mask, const float* __restrict__ group,
    float* __restrict__ gm)
{
    const int t = blockIdx.x * 256 + threadIdx.x;
    if (t >= BATCH * SEQ * SEQ / 4) return;
    const int i = t * 4;
    const int q = (i >> 10) & 1023;
    const int k = i & 1023;
    const int4   mk = *(const int4*)(mask + i);
    const float4 gr = *(const float4*)(group + i);
    float4 o;
    o.x = (mk.x || q == k + 0) ? gr.x : -1.0f;
    o.y = (mk.y || q == k + 1) ? gr.y : -1.0f;
    o.z = (mk.z || q == k + 2) ? gr.z : -1.0f;
    o.w = (mk.w || q == k + 3) ? gr.w : -1.0f;
    *(float4*)(gm + i) = o;
}

// ---------------------------------------------------------------------------
// bf16x3 GEMM. CTA tile 128x256, BK=64, 2 stages, 512 threads,
// 16 warps (4M x 4N, 32x64 warp tile). out[r,c] = sum_k A[r,k]*W[c,k] + bias[c]
// ---------------------------------------------------------------------------
#define GEMM_THREADS 512
#define BM 128
#define BN 256
#define BK 64
#define KTILES (DMODEL / BK)          // 16
#define PAD_B 144                     // bytes per smem row (128 data + 16 pad)
#define TILE_AB (128 * PAD_B)         // 18432
#define TILE_BB (256 * PAD_B)         // 36864
#define OFF_AL  TILE_AB
#define OFF_BH  (2 * TILE_AB)
#define OFF_BL  (2 * TILE_AB + TILE_BB)
#define STAGE_B (2 * TILE_AB + 2 * TILE_BB)   // 110592
#define GEMM_SMEM (2 * STAGE_B)               // 221184

__device__ __forceinline__ void gemm_body(
    const __nv_bfloat16* __restrict__ aH, const __nv_bfloat16* __restrict__ aL,
    const __nv_bfloat16* __restrict__ bH, const __nv_bfloat16* __restrict__ bL,
    const float* __restrict__ bias, float* __restrict__ outF,
    __nv_bfloat16* __restrict__ outH, __nv_bfloat16* __restrict__ outL,
    int mode, float oscale, int brow, int bcol, char* smem)
{
    const uint32_t sb = s2u(smem);
    const int tid  = threadIdx.x;
    const int lane = tid & 31;
    const int wid  = tid >> 5;
    const int warpM = wid >> 2;          // 0..3
    const int warpN = wid & 3;           // 0..3

    float acc[2][8][4];
#pragma unroll
    for (int i = 0; i < 2; i++)
#pragma unroll
        for (int j = 0; j < 8; j++)
#pragma unroll
            for (int k = 0; k < 4; k++) acc[i][j][k] = 0.0f;

    auto load_stage = [&](int kb, int s) {
        const int k0 = kb * BK;
        const uint32_t base = sb + (uint32_t)s * STAGE_B;
        // A: 128 rows x 8 chunks (hi+lo) = 1024 chunks each
#pragma unroll
        for (int i = 0; i < 2; i++) {
            const int c = tid + i * GEMM_THREADS;   // 0..1023
            const int r = c >> 3;
            const int q = c & 7;
            const uint32_t dst = base + (uint32_t)r * PAD_B + q * 16;
            const size_t aoff = (size_t)(brow + r) * DMODEL + k0 + q * 8;
            cp16(dst,          aH + aoff);
            cp16(dst + OFF_AL, aL + aoff);
        }
        // B: 256 rows x 8 chunks (hi+lo) = 2048 chunks each
#pragma unroll
        for (int i = 0; i < 4; i++) {
            const int c = tid + i * GEMM_THREADS;   // 0..2047
            const int r = c >> 3;
            const int q = c & 7;
            const uint32_t dst = base + OFF_BH + (uint32_t)r * PAD_B + q * 16;
            const size_t boff = (size_t)(bcol + r) * DMODEL + k0 + q * 8;
            cp16(dst,                     bH + boff);
            cp16(dst + (OFF_BL - OFF_BH), bL + boff);
        }
        asm volatile("cp.async.commit_group;" ::: "memory");
    };

    const int l8 = lane & 7, lg = lane >> 3;
    const int a_row_off = ((lg & 1) ? 8 : 0) + l8;
    const int a_col_off = (lg & 2) ? 8 : 0;
    const int b_row_off = ((lg >> 1) ? 8 : 0) + l8;
    const int b_col_off = (lg & 1) ? 8 : 0;

    load_stage(0, 0);
    load_stage(1, 1);
    asm volatile("cp.async.wait_group 1;" ::: "memory");
    __syncthreads();

    for (int kb = 0; kb < KTILES; kb++) {
        const uint32_t stg = sb + (uint32_t)(kb & 1) * STAGE_B;
#pragma unroll
        for (int ks = 0; ks < 4; ks++) {
            // A fragments for this warp's 32 rows (2 x 16-row tiles), hi+lo
            uint32_t ah[2][4], al[2][4];
#pragma unroll
            for (int mt = 0; mt < 2; mt++) {
                const int row = warpM * 32 + mt * 16 + a_row_off;
                const int col = ks * 16 + a_col_off;
                const uint32_t ad = stg + (uint32_t)row * PAD_B + col * 2;
                ldm_x4(ah[mt], ad);
                ldm_x4(al[mt], ad + OFF_AL);
            }
#pragma unroll
            for (int pt = 0; pt < 4; pt++) {
                const int n   = warpN * 64 + pt * 16 + b_row_off;
                const int col = ks * 16 + b_col_off;
                const uint32_t bd = stg + OFF_BH + (uint32_t)n * PAD_B + col * 2;
                uint32_t th[4], tl[4];
                ldm_x4(th, bd);
                ldm_x4(tl, bd + (OFF_BL - OFF_BH));
                uint32_t bh0[2] = {th[0], th[1]}, bh1[2] = {th[2], th[3]};
                uint32_t bl0[2] = {tl[0], tl[1]}, bl1[2] = {tl[2], tl[3]};
#pragma unroll
                for (int mt = 0; mt < 2; mt++) {
                    mma_bf16(acc[mt][pt * 2],     ah[mt], bh0);
                    mma_bf16(acc[mt][pt * 2],     ah[mt], bl0);
                    mma_bf16(acc[mt][pt * 2],     al[mt], bh0);
                    mma_bf16(acc[mt][pt * 2 + 1], ah[mt], bh1);
                    mma_bf16(acc[mt][pt * 2 + 1], ah[mt], bl1);
                    mma_bf16(acc[mt][pt * 2 + 1], al[mt], bh1);
                }
            }
        }
        __syncthreads();  // all warps done reading this stage
        if (kb + 2 < KTILES) load_stage(kb + 2, kb & 1);
        else asm volatile("cp.async.commit_group;" ::: "memory");
        if (kb + 1 < KTILES) {
            asm volatile("cp.async.wait_group 1;" ::: "memory");
            __syncthreads();
        }
    }

#pragma unroll
    for (int mt = 0; mt < 2; mt++) {
        const int row = brow + warpM * 32 + mt * 16 + (lane >> 2);
#pragma unroll
        for (int nt = 0; nt < 8; nt++) {
            const int col = bcol + warpN * 64 + (nt >> 1) * 16 + (nt & 1) * 8
                          + (lane & 3) * 2;
            const float b0 = bias[col], b1 = bias[col + 1];
            const float v00 = acc[mt][nt][0] + b0, v01 = acc[mt][nt][1] + b1;
            const float v10 = acc[mt][nt][2] + b0, v11 = acc[mt][nt][3] + b1;
            if (mode == 0) {
                *(float2*)(outF + (size_t)row * DMODEL + col) = make_float2(v00, v01);
                *(float2*)(outF + (size_t)(row + 8) * DMODEL + col) = make_float2(v10, v11);
            } else {
                const int h = col >> 6, dk = col & 63;
                const int bi = row >> 10, s = row & 1023;
                const size_t d0 = (((size_t)(bi * NHEAD + h)) * SEQ + s) * DHEAD + dk;
                uint32_t hi, lo;
                split2(v00 * oscale, v01 * oscale, hi, lo);
                *(uint32_t*)(outH + d0) = hi;
                *(uint32_t*)(outL + d0) = lo;
                split2(v10 * oscale, v11 * oscale, hi, lo);
                *(uint32_t*)(outH + d0 + 8 * DHEAD) = hi;
                *(uint32_t*)(outL + d0 + 8 * DHEAD) = lo;
            }
        }
    }
}

__global__ __launch_bounds__(GEMM_THREADS, 1) void gemm_qkv_kernel(
    const float* __restrict__ bq, const float* __restrict__ bk,
    const float* __restrict__ bv, float qscale)
{
    extern __shared__ __align__(16) char smem[];
    const int z = blockIdx.z;
    const __nv_bfloat16 *aH, *aL, *bH, *bL;
    __nv_bfloat16 *oH, *oL;
    const float* bias;
    float sc;
    if (z == 0)      { aH = g_qh; aL = g_ql; bH = g_wqh; bL = g_wql;
                       oH = g_oqh; oL = g_oql; bias = bq; sc = qscale; }
    else if (z == 1) { aH = g_kh; aL = g_kl; bH = g_wkh; bL = g_wkl;
                       oH = g_okh; oL = g_okl; bias = bk; sc = 1.0f; }
    else             { aH = g_vh; aL = g_vl; bH = g_wvh; bL = g_wvl;
                       oH = g_ovh; oL = g_ovl; bias = bv; sc = 1.0f; }
    gemm_body(aH, aL, bH, bL, bias, nullptr, oH, oL, 1, sc,
              blockIdx.y * BM, blockIdx.x * BN, smem);
}

__global__ __launch_bounds__(GEMM_THREADS, 1) void gemm_out_kernel(
    const float* __restrict__ bo, float* __restrict__ out)
{
    extern __shared__ __align__(16) char smem[];
    gemm_body(g_ch, g_cl, g_woh, g_wol, bo, out, nullptr, nullptr, 0, 1.0f,
              blockIdx.y * BM, blockIdx.x * BN, smem);
}

// ---------------------------------------------------------------------------
// Tensor-core flash attention (unchanged)
// ---------------------------------------------------------------------------
#define ATT_QH 0
#define ATT_QL 16384
#define ATT_STG0 32768
#define ATT_STG_B 32768
#define ATT_SMEM (32768 + 2 * ATT_STG_B)   // 98304

__global__ __launch_bounds__(256, 2) void attn_kernel(const float* __restrict__ gm)
{
    extern __shared__ __align__(16) char smem[];
    const uint32_t sb = s2u(smem);
    const int tid  = threadIdx.x;
    const int lane = tid & 31;
    const int w    = tid >> 5;
    const int h    = blockIdx.x;
    const int q0   = blockIdx.y * 128;
    const int b    = blockIdx.z;
    const int bh   = b * NHEAD + h;

    const __nv_bfloat16* Qh = g_oqh + ((size_t)bh * SEQ + q0) * DHEAD;
    const __nv_bfloat16* Ql = g_oql + ((size_t)bh * SEQ + q0) * DHEAD;
    const __nv_bfloat16* Kh = g_okh + (size_t)bh * SEQ * DHEAD;
    const __nv_bfloat16* Kl = g_okl + (size_t)bh * SEQ * DHEAD;
    const __nv_bfloat16* Vh = g_ovh + (size_t)bh * SEQ * DHEAD;
    const __nv_bfloat16* Vl = g_ovl + (size_t)bh * SEQ * DHEAD;

#pragma unroll
    for (int i = 0; i < 4; i++) {
        const int c = tid + i * 256;
        const int r = c >> 3, off = c & 7;
        const uint32_t d = swz((uint32_t)r * 128 + off * 16);
        cp16(sb + ATT_QH + d, Qh + (size_t)r * DHEAD + off * 8);
        cp16(sb + ATT_QL + d, Ql + (size_t)r * DHEAD + off * 8);
    }
    auto load_stage = [&](int kt, int s) {
        const int k0 = kt * 64;
        const uint32_t base = sb + ATT_STG0 + (uint32_t)s * ATT_STG_B;
#pragma unroll
        for (int i = 0; i < 2; i++) {
            const int c = tid + i * 256;
            const int r = c >> 3, off = c & 7;
            const uint32_t d = swz((uint32_t)r * 128 + off * 16);
            const size_t g = (size_t)(k0 + r) * DHEAD + off * 8;
            cp16(base + d,         Kh + g);
            cp16(base + 8192 + d,  Kl + g);
            cp16(base + 16384 + d, Vh + g);
            cp16(base + 24576 + d, Vl + g);
        }
    };
    load_stage(0, 0);
    asm volatile("cp.async.commit_group;" ::: "memory");
    load_stage(1, 1);
    asm volatile("cp.async.commit_group;" ::: "memory");
    asm volatile("cp.async.wait_group 1;" ::: "memory");
    __syncthreads();

    const int l8 = lane & 7, lg = lane >> 3;
    const int a_row_off = ((lg & 1) ? 8 : 0) + l8;
    const int a_col_off = (lg & 2) ? 8 : 0;
    const int b_row_off = ((lg >> 1) ? 8 : 0) + l8;
    const int b_col_off = (lg & 1) ? 8 : 0;

    uint32_t qfh[4][4];
    const uint32_t qrowbyte = (uint32_t)(w * 16 + a_row_off) * 128;
#pragma unroll
    for (int ks = 0; ks < 4; ks++) {
        const uint32_t d = swz(qrowbyte + (ks * 16 + a_col_off) * 2);
        ldm_x4(qfh[ks], sb + ATT_QH + d);
    }

    float accv[8][4];
#pragma unroll
    for (int i = 0; i < 8; i++)
#pragma unroll
        for (int j = 0; j < 4; j++) accv[i][j] = 0.0f;
    float m0 = -INFINITY, m1 = -INFINITY, l0 = 0.0f, l1 = 0.0f;

    const int r0 = lane >> 2;
    const int qrow0 = q0 + w * 16 + r0;
    const float* gmRow0 = gm + ((size_t)b * SEQ + qrow0) * SEQ;
    const float* gmRow1 = gmRow0 + 8 * SEQ;
    const int colq = (lane & 3) * 2;

    for (int kt = 0; kt < SEQ / 64; kt++) {
        const int st = kt & 1;
        const uint32_t stg = sb + ATT_STG0 + (uint32_t)st * ATT_STG_B;

        float s[8][4];
#pragma unroll
        for (int i = 0; i < 8; i++)
#pragma unroll
            for (int j = 0; j < 4; j++) s[i][j] = 0.0f;
#pragma unroll
        for (int ks = 0; ks < 4; ks++) {
            uint32_t qfl[4];
            ldm_x4(qfl, sb + ATT_QL + swz(qrowbyte + (ks * 16 + a_col_off) * 2));
#pragma unroll
            for (int g16 = 0; g16 < 4; g16++) {
                const int row = g16 * 16 + b_row_off;
                const int col = ks * 16 + b_col_off;
                const uint32_t d = swz((uint32_t)row * 128 + col * 2);
                uint32_t kh4[4], kl4[4];
                ldm_x4(kh4, stg + d);
                ldm_x4(kl4, stg + 8192 + d);
                uint32_t bh0[2] = {kh4[0], kh4[1]}, bh1[2] = {kh4[2], kh4[3]};
                uint32_t bl0[2] = {kl4[0], kl4[1]}, bl1[2] = {kl4[2], kl4[3]};
                mma_bf16(s[g16 * 2],     qfh[ks], bh0);
                mma_bf16(s[g16 * 2],     qfh[ks], bl0);
                mma_bf16(s[g16 * 2],     qfl,     bh0);
                mma_bf16(s[g16 * 2 + 1], qfh[ks], bh1);
                mma_bf16(s[g16 * 2 + 1], qfh[ks], bl1);
                mma_bf16(s[g16 * 2 + 1], qfl,     bh1);
            }
        }

        float rm0 = -INFINITY, rm1 = -INFINITY;
#pragma unroll
        for (int nt = 0; nt < 8; nt++) {
            rm0 = fmaxf(rm0, fmaxf(s[nt][0], s[nt][1]));
            rm1 = fmaxf(rm1, fmaxf(s[nt][2], s[nt][3]));
        }
        rm0 = fmaxf(rm0, __shfl_xor_sync(0xffffffffu, rm0, 1));
        rm0 = fmaxf(rm0, __shfl_xor_sync(0xffffffffu, rm0, 2));
        rm1 = fmaxf(rm1, __shfl_xor_sync(0xffffffffu, rm1, 1));
        rm1 = fmaxf(rm1, __shfl_xor_sync(0xffffffffu, rm1, 2));
        const float m0n = fmaxf(m0, rm0);
        const float m1n = fmaxf(m1, rm1);
        const float c0 = ex2(m0 - m0n);
        const float c1 = ex2(m1 - m1n);
        l0 *= c0; l1 *= c1;
        m0 = m0n; m1 = m1n;
#pragma unroll
        for (int nt = 0; nt < 8; nt++) {
            accv[nt][0] *= c0; accv[nt][1] *= c0;
            accv[nt][2] *= c1; accv[nt][3] *= c1;
        }

        uint32_t aPh[4][4], aPl[4][4];
        const int kbase = kt * 64 + colq;
#pragma unroll
        for (int nt = 0; nt < 8; nt++) {
            const int kc = kbase + nt * 8;
            const float2 g0 = *(const float2*)(gmRow0 + kc);
            const float2 g1 = *(const float2*)(gmRow1 + kc);
            const float p00 = ex2(s[nt][0] - m0);
            const float p01 = ex2(s[nt][1] - m0);
            const float p10 = ex2(s[nt][2] - m1);
            const float p11 = ex2(s[nt][3] - m1);
            l0 += (g0.x >= 0.0f ? p00 : 0.0f) + (g0.y >= 0.0f ? p01 : 0.0f);
            l1 += (g1.x >= 0.0f ? p10 : 0.0f) + (g1.y >= 0.0f ? p11 : 0.0f);
            const float w00 = p00 * fmaxf(g0.x, 0.0f);
            const float w01 = p01 * fmaxf(g0.y, 0.0f);
            const float w10 = p10 * fmaxf(g1.x, 0.0f);
            const float w11 = p11 * fmaxf(g1.y, 0.0f);
            const int ks = nt >> 1, half = (nt & 1) * 2;
            split2(w00, w01, aPh[ks][half + 0], aPl[ks][half + 0]);
            split2(w10, w11, aPh[ks][half + 1], aPl[ks][half + 1]);
        }

#pragma unroll
        for (int ks = 0; ks < 4; ks++) {
#pragma unroll
            for (int ng = 0; ng < 4; ng++) {
                const int row = ks * 16 + ((lg & 1) ? 8 : 0) + l8;
                const int col = ng * 16 + ((lg >> 1) ? 8 : 0);
                const uint32_t d = swz((uint32_t)row * 128 + col * 2);
                uint32_t vh4[4], vl4[4];
                ldm_x4_t(vh4, stg + 16384 + d);
                ldm_x4_t(vl4, stg + 24576 + d);
                uint32_t bh0[2] = {vh4[0], vh4[1]}, bh1[2] = {vh4[2], vh4[3]};
                uint32_t bl0[2] = {vl4[0], vl4[1]}, bl1[2] = {vl4[2], vl4[3]};
                mma_bf16(accv[ng * 2],     aPh[ks], bh0);
                mma_bf16(accv[ng * 2],     aPh[ks], bl0);
                mma_bf16(accv[ng * 2],     aPl[ks], bh0);
                mma_bf16(accv[ng * 2 + 1], aPh[ks], bh1);
                mma_bf16(accv[ng * 2 + 1], aPh[ks], bl1);
                mma_bf16(accv[ng * 2 + 1], aPl[ks], bh1);
            }
        }

        __syncthreads();
        if (kt + 2 < SEQ / 64) load_stage(kt + 2, st);
        asm volatile("cp.async.commit_group;" ::: "memory");
        if (kt + 1 < SEQ / 64) {
            asm volatile("cp.async.wait_group 1;" ::: "memory");
            __syncthreads();
        }
    }

    l0 += __shfl_xor_sync(0xffffffffu, l0, 1);
    l0 += __shfl_xor_sync(0xffffffffu, l0, 2);
    l1 += __shfl_xor_sync(0xffffffffu, l1, 1);
    l1 += __shfl_xor_sync(0xffffffffu, l1, 2);
    const float inv0 = 1.0f / l0, inv1 = 1.0f / l1;

    const size_t tok0 = (size_t)b * SEQ + qrow0;
    __nv_bfloat16* ch0 = g_ch + tok0 * DMODEL + h * DHEAD + colq;
    __nv_bfloat16* cl0 = g_cl + tok0 * DMODEL + h * DHEAD + colq;
#pragma unroll
    for (int nt = 0; nt < 8; nt++) {
        uint32_t hi, lo;
        split2(accv[nt][0] * inv0, accv[nt][1] * inv0, hi, lo);
        *(uint32_t*)(ch0 + nt * 8) = hi;
        *(uint32_t*)(cl0 + nt * 8) = lo;
        split2(accv[nt][2] * inv1, accv[nt][3] * inv1, hi, lo);
        *(uint32_t*)(ch0 + 8 * DMODEL + nt * 8) = hi;
        *(uint32_t*)(cl0 + 8 * DMODEL + nt * 8) = lo;
    }
}

// ---------------------------------------------------------------------------
extern "C" void kernel_launch(void* const* d_in, const int* in_sizes, int n_in,
                              void* d_out, int out_size)
{
    (void)in_sizes; (void)n_in; (void)out_size;
    const float* query = (const float*)d_in[0];
    const float* key_  = (const float*)d_in[1];
    const float* value = (const float*)d_in[2];
    const int*   mask  = (const int*)  d_in[3];
    const float* group = (const float*)d_in[4];
    const float* Wq = (const float*)d_in[5];
    const float* bq = (const float*)d_in[6];
    const float* Wk = (const float*)d_in[7];
    const float* bk = (const float*)d_in[8];
    const float* Wv = (const float*)d_in[9];
    const float* bv = (const float*)d_in[10];
    const float* Wo = (const float*)d_in[11];
    const float* bo = (const float*)d_in[12];
    float* out = (float*)d_out;

    float* gmp;
    cudaGetSymbolAddress((void**)&gmp, g_gm);

    cudaFuncSetAttribute(gemm_qkv_kernel, cudaFuncAttributeMaxDynamicSharedMemorySize,
                         GEMM_SMEM);
    cudaFuncSetAttribute(gemm_out_kernel, cudaFuncAttributeMaxDynamicSharedMemorySize,
                         GEMM_SMEM);
    cudaFuncSetAttribute(attn_kernel, cudaFuncAttributeMaxDynamicSharedMemorySize,
                         ATT_SMEM);

    cvt_act_kernel<<<dim3(NTOK * (DMODEL / 8) / 256, 3), 256>>>(query, key_, value);
    cvt_w_kernel<<<dim3(DMODEL * (DMODEL / 8) / 256, 4), 256>>>(Wq, Wk, Wv, Wo);
    prep_gm_kernel<<<BATCH * SEQ * SEQ / 4 / 256, 256>>>(mask, group, gmp);

    const float QSCALE = 0.125f * 1.44269504088896f;  // 1/sqrt(DK) * log2(e)
    gemm_qkv_kernel<<<dim3(DMODEL / BN, NTOK / BM, 3), GEMM_THREADS, GEMM_SMEM>>>(
        bq, bk, bv, QSCALE);

    attn_kernel<<<dim3(NHEAD, SEQ / 128, BATCH), 256, ATT_SMEM>>>(gmp);

    gemm_out_kernel<<<dim3(DMODEL / BN, NTOK / BM), GEMM_THREADS, GEMM_SMEM>>>(bo, out);
}

// round 9
// speedup vs baseline: 1.2933x; 1.2933x over previous
#include <cuda_runtime.h>
#include <cuda_fp16.h>
#include <math.h>
#include <stdint.h>

#define BATCH  4
#define SEQ    1024
#define DMODEL 1024
#define NHEAD  16
#define DHEAD  64
#define NTOK   (BATCH * SEQ)

// ---------------- scratch (device globals; no runtime alloc) ----------------
// activations: fp16 hi only (2-pass scheme corrects the weight side)
__device__ __half g_qa[NTOK * DMODEL], g_ka[NTOK * DMODEL], g_va[NTOK * DMODEL];
// weights: fp16 hi + lo
__device__ __half g_wqh[DMODEL * DMODEL], g_wql[DMODEL * DMODEL];
__device__ __half g_wkh[DMODEL * DMODEL], g_wkl[DMODEL * DMODEL];
__device__ __half g_wvh[DMODEL * DMODEL], g_wvl[DMODEL * DMODEL];
__device__ __half g_woh[DMODEL * DMODEL], g_wol[DMODEL * DMODEL];
// projected Q (hi only; Q residual dropped), K/V hi+lo, [b,h,s,64] layout
__device__ __half g_oqh[NTOK * DMODEL];
__device__ __half g_okh[NTOK * DMODEL], g_okl[NTOK * DMODEL];
__device__ __half g_ovh[NTOK * DMODEL], g_ovl[NTOK * DMODEL];
// attention context, fp16 hi only, row-major [tok][1024]
__device__ __half g_ch[NTOK * DMODEL];
// fused mask*group: allowed ? group : -1
__device__ float g_gm[BATCH * SEQ * SEQ];

// ---------------------------------------------------------------------------
// shared PTX helpers
// ---------------------------------------------------------------------------
__device__ __forceinline__ uint32_t s2u(const void* p) {
    uint32_t a;
    asm("{ .reg .u64 t; cvta.to.shared.u64 t, %1; cvt.u32.u64 %0, t; }"
        : "=r"(a) : "l"(p));
    return a;
}
__device__ __forceinline__ void cp16(uint32_t dst, const void* src) {
    asm volatile("cp.async.cg.shared.global [%0], [%1], 16;" :: "r"(dst), "l"(src));
}
__device__ __forceinline__ void ldm_x4(uint32_t* r, uint32_t addr) {
    asm volatile("ldmatrix.sync.aligned.m8n8.x4.shared.b16 {%0,%1,%2,%3}, [%4];"
                 : "=r"(r[0]), "=r"(r[1]), "=r"(r[2]), "=r"(r[3]) : "r"(addr));
}
__device__ __forceinline__ void ldm_x4_t(uint32_t* r, uint32_t addr) {
    asm volatile("ldmatrix.sync.aligned.m8n8.x4.trans.shared.b16 {%0,%1,%2,%3}, [%4];"
                 : "=r"(r[0]), "=r"(r[1]), "=r"(r[2]), "=r"(r[3]) : "r"(addr));
}
__device__ __forceinline__ void mma_f16(float* c, const uint32_t* a,
                                        const uint32_t* b) {
    asm volatile(
        "mma.sync.aligned.m16n8k16.row.col.f32.f16.f16.f32 "
        "{%0,%1,%2,%3}, {%4,%5,%6,%7}, {%8,%9}, {%0,%1,%2,%3};"
        : "+f"(c[0]), "+f"(c[1]), "+f"(c[2]), "+f"(c[3])
        : "r"(a[0]), "r"(a[1]), "r"(a[2]), "r"(a[3]), "r"(b[0]), "r"(b[1]));
}
__device__ __forceinline__ uint32_t swz(uint32_t byte) {
    return byte ^ ((byte >> 3) & 0x70);
}
// pack two fp32 -> f16x2 (x in low half)
__device__ __forceinline__ uint32_t pack_h2(float x, float y) {
    uint32_t r;
    asm("cvt.rn.f16x2.f32 %0, %1, %2;" : "=r"(r) : "f"(y), "f"(x));
    return r;
}
__device__ __forceinline__ void split2h(float x, float y, uint32_t& hi, uint32_t& lo) {
    hi = pack_h2(x, y);
    const __half2 h = *(const __half2*)&hi;
    const float2 f = __half22float2(h);
    lo = pack_h2(x - f.x, y - f.y);
}
__device__ __forceinline__ float ex2(float x) {
    float r;
    asm("ex2.approx.f32 %0, %1;" : "=f"(r) : "f"(x));
    return r;
}

// ---------------------------------------------------------------------------
// conversions
// ---------------------------------------------------------------------------
// activations: fp16 hi only. z=0 query, 1 key, 2 value
__global__ __launch_bounds__(256) void cvt_act_kernel(
    const float* __restrict__ s0, const float* __restrict__ s1,
    const float* __restrict__ s2)
{
    const int t = blockIdx.x * 256 + threadIdx.x;
    if (t >= NTOK * (DMODEL / 8)) return;
    const int z = blockIdx.y;
    const float* src = (z == 0) ? s0 : (z == 1) ? s1 : s2;
    __half* dst = (z == 0) ? g_qa : (z == 1) ? g_ka : g_va;
    const int idx = t * 8;
    const float4 a = *(const float4*)(src + idx);
    const float4 b = *(const float4*)(src + idx + 4);
    uint4 o;
    o.x = pack_h2(a.x, a.y);
    o.y = pack_h2(a.z, a.w);
    o.z = pack_h2(b.x, b.y);
    o.w = pack_h2(b.z, b.w);
    *(uint4*)(dst + idx) = o;
}

// weights: fp16 hi + lo. z=0 Wq, 1 Wk, 2 Wv, 3 Wo
__global__ __launch_bounds__(256) void cvt_w_kernel(
    const float* __restrict__ s0, const float* __restrict__ s1,
    const float* __restrict__ s2, const float* __restrict__ s3)
{
    const int t = blockIdx.x * 256 + threadIdx.x;
    if (t >= DMODEL * (DMODEL / 8)) return;
    const int z = blockIdx.y;
    const float* src = (z == 0) ? s0 : (z == 1) ? s1 : (z == 2) ? s2 : s3;
    __half* hi = (z == 0) ? g_wqh : (z == 1) ? g_wkh : (z == 2) ? g_wvh : g_woh;
    __half* lo = (z == 0) ? g_wql : (z == 1) ? g_wkl : (z == 2) ? g_wvl : g_wol;
    const int idx = t * 8;
    const float4 a = *(const float4*)(src + idx);
    const float4 b = *(const float4*)(src + idx + 4);
    const float f[8] = {a.x, a.y, a.z, a.w, b.x, b.y, b.z, b.w};
    uint4 oh, ol;
    split2h(f[0], f[1], oh.x, ol.x);
    split2h(f[2], f[3], oh.y, ol.y);
    split2h(f[4], f[5], oh.z, ol.z);
    split2h(f[6], f[7], oh.w, ol.w);
    *(uint4*)(hi + idx) = oh;
    *(uint4*)(lo + idx) = ol;
}

// gm = (mask || q==k) ? group : -1
__global__ __launch_bounds__(256) void prep_gm_kernel(
    const int* __restrict__ mask, const float* __restrict__ group,
    float* __restrict__ gm)
{
    const int t = blockIdx.x * 256 + threadIdx.x;
    if (t >= BATCH * SEQ * SEQ / 4) return;
    const int i = t * 4;
    const int q = (i >> 10) & 1023;
    const int k = i & 1023;
    const int4   mk = *(const int4*)(mask + i);
    const float4 gr = *(const float4*)(group + i);
    float4 o;
    o.x = (mk.x || q == k + 0) ? gr.x : -1.0f;
    o.y = (mk.y || q == k + 1) ? gr.y : -1.0f;
    o.z = (mk.z || q == k + 2) ? gr.z : -1.0f;
    o.w = (mk.w || q == k + 3) ? gr.w : -1.0f;
    *(float4*)(gm + i) = o;
}

// ---------------------------------------------------------------------------
// fp16x2 GEMM: out[r,c] = sum_k A[r,k] * (Wh[c,k]+Wl[c,k]) + bias[c]
// CTA tile 128x256, BK=64, 2 stages, 512 threads (16 warps, 32x64 warp tile).
// ---------------------------------------------------------------------------
#define GEMM_THREADS 512
#define BM 128
#define BN 256
#define BK 64
#define KTILES (DMODEL / BK)          // 16
#define PAD_B 144
#define TILE_AB (128 * PAD_B)         // 18432
#define TILE_BB (256 * PAD_B)         // 36864
#define OFF_BH  TILE_AB
#define OFF_BL  (TILE_AB + TILE_BB)
#define STAGE_B (TILE_AB + 2 * TILE_BB)   // 92160
#define GEMM_SMEM (2 * STAGE_B)           // 184320

__device__ __forceinline__ void gemm_body(
    const __half* __restrict__ aH,
    const __half* __restrict__ bH, const __half* __restrict__ bL,
    const float* __restrict__ bias, float* __restrict__ outF,
    __half* __restrict__ outH, __half* __restrict__ outL,
    int mode, int write_lo, float oscale, int brow, int bcol, char* smem)
{
    const uint32_t sb = s2u(smem);
    const int tid  = threadIdx.x;
    const int lane = tid & 31;
    const int wid  = tid >> 5;
    const int warpM = wid >> 2;          // 0..3
    const int warpN = wid & 3;           // 0..3

    float acc[2][8][4];
#pragma unroll
    for (int i = 0; i < 2; i++)
#pragma unroll
        for (int j = 0; j < 8; j++)
#pragma unroll
            for (int k = 0; k < 4; k++) acc[i][j][k] = 0.0f;

    auto load_stage = [&](int kb, int s) {
        const int k0 = kb * BK;
        const uint32_t base = sb + (uint32_t)s * STAGE_B;
#pragma unroll
        for (int i = 0; i < 2; i++) {
            const int c = tid + i * GEMM_THREADS;   // 0..1023
            const int r = c >> 3;
            const int q = c & 7;
            cp16(base + (uint32_t)r * PAD_B + q * 16,
                 aH + (size_t)(brow + r) * DMODEL + k0 + q * 8);
        }
#pragma unroll
        for (int i = 0; i < 4; i++) {
            const int c = tid + i * GEMM_THREADS;   // 0..2047
            const int r = c >> 3;
            const int q = c & 7;
            const uint32_t dst = base + OFF_BH + (uint32_t)r * PAD_B + q * 16;
            const size_t boff = (size_t)(bcol + r) * DMODEL + k0 + q * 8;
            cp16(dst,           bH + boff);
            cp16(dst + TILE_BB, bL + boff);
        }
        asm volatile("cp.async.commit_group;" ::: "memory");
    };

    const int l8 = lane & 7, lg = lane >> 3;
    const int a_row_off = ((lg & 1) ? 8 : 0) + l8;
    const int a_col_off = (lg & 2) ? 8 : 0;
    const int b_row_off = ((lg >> 1) ? 8 : 0) + l8;
    const int b_col_off = (lg & 1) ? 8 : 0;

    load_stage(0, 0);
    load_stage(1, 1);
    asm volatile("cp.async.wait_group 1;" ::: "memory");
    __syncthreads();

    for (int kb = 0; kb < KTILES; kb++) {
        const uint32_t stg = sb + (uint32_t)(kb & 1) * STAGE_B;
#pragma unroll
        for (int ks = 0; ks < 4; ks++) {
            uint32_t ah[2][4];
#pragma unroll
            for (int mt = 0; mt < 2; mt++) {
                const int row = warpM * 32 + mt * 16 + a_row_off;
                const int col = ks * 16 + a_col_off;
                ldm_x4(ah[mt], stg + (uint32_t)row * PAD_B + col * 2);
            }
#pragma unroll
            for (int pt = 0; pt < 4; pt++) {
                const int n   = warpN * 64 + pt * 16 + b_row_off;
                const int col = ks * 16 + b_col_off;
                const uint32_t bd = stg + OFF_BH + (uint32_t)n * PAD_B + col * 2;
                uint32_t th[4], tl[4];
                ldm_x4(th, bd);
                ldm_x4(tl, bd + TILE_BB);
                uint32_t bh0[2] = {th[0], th[1]}, bh1[2] = {th[2], th[3]};
                uint32_t bl0[2] = {tl[0], tl[1]}, bl1[2] = {tl[2], tl[3]};
#pragma unroll
                for (int mt = 0; mt < 2; mt++) {
                    mma_f16(acc[mt][pt * 2],     ah[mt], bh0);
                    mma_f16(acc[mt][pt * 2],     ah[mt], bl0);
                    mma_f16(acc[mt][pt * 2 + 1], ah[mt], bh1);
                    mma_f16(acc[mt][pt * 2 + 1], ah[mt], bl1);
                }
            }
        }
        __syncthreads();
        if (kb + 2 < KTILES) load_stage(kb + 2, kb & 1);
        else asm volatile("cp.async.commit_group;" ::: "memory");
        if (kb + 1 < KTILES) {
            asm volatile("cp.async.wait_group 1;" ::: "memory");
            __syncthreads();
        }
    }

#pragma unroll
    for (int mt = 0; mt < 2; mt++) {
        const int row = brow + warpM * 32 + mt * 16 + (lane >> 2);
#pragma unroll
        for (int nt = 0; nt < 8; nt++) {
            const int col = bcol + warpN * 64 + (nt >> 1) * 16 + (nt & 1) * 8
                          + (lane & 3) * 2;
            const float b0 = bias[col], b1 = bias[col + 1];
            const float v00 = acc[mt][nt][0] + b0, v01 = acc[mt][nt][1] + b1;
            const float v10 = acc[mt][nt][2] + b0, v11 = acc[mt][nt][3] + b1;
            if (mode == 0) {
                *(float2*)(outF + (size_t)row * DMODEL + col) = make_float2(v00, v01);
                *(float2*)(outF + (size_t)(row + 8) * DMODEL + col) = make_float2(v10, v11);
            } else {
                const int h = col >> 6, dk = col & 63;
                const int bi = row >> 10, s = row & 1023;
                const size_t d0 = (((size_t)(bi * NHEAD + h)) * SEQ + s) * DHEAD + dk;
                if (write_lo) {
                    uint32_t hi, lo;
                    split2h(v00 * oscale, v01 * oscale, hi, lo);
                    *(uint32_t*)(outH + d0) = hi;
                    *(uint32_t*)(outL + d0) = lo;
                    split2h(v10 * oscale, v11 * oscale, hi, lo);
                    *(uint32_t*)(outH + d0 + 8 * DHEAD) = hi;
                    *(uint32_t*)(outL + d0 + 8 * DHEAD) = lo;
                } else {
                    *(uint32_t*)(outH + d0) = pack_h2(v00 * oscale, v01 * oscale);
                    *(uint32_t*)(outH + d0 + 8 * DHEAD) = pack_h2(v10 * oscale, v11 * oscale);
                }
            }
        }
    }
}

__global__ __launch_bounds__(GEMM_THREADS, 1) void gemm_qkv_kernel(
    const float* __restrict__ bq, const float* __restrict__ bk,
    const float* __restrict__ bv, float qscale)
{
    extern __shared__ __align__(16) char smem[];
    const int z = blockIdx.z;
    const __half *aH, *bH, *bL;
    __half *oH, *oL;
    const float* bias;
    float sc;
    int wl;
    if (z == 0)      { aH = g_qa; bH = g_wqh; bL = g_wql;
                       oH = g_oqh; oL = g_oqh; bias = bq; sc = qscale; wl = 0; }
    else if (z == 1) { aH = g_ka; bH = g_wkh; bL = g_wkl;
                       oH = g_okh; oL = g_okl; bias = bk; sc = 1.0f; wl = 1; }
    else             { aH = g_va; bH = g_wvh; bL = g_wvl;
                       oH = g_ovh; oL = g_ovl; bias = bv; sc = 1.0f; wl = 1; }
    gemm_body(aH, bH, bL, bias, nullptr, oH, oL, 1, wl, sc,
              blockIdx.y * BM, blockIdx.x * BN, smem);
}

__global__ __launch_bounds__(GEMM_THREADS, 1) void gemm_out_kernel(
    const float* __restrict__ bo, float* __restrict__ out)
{
    extern __shared__ __align__(16) char smem[];
    gemm_body(g_ch, g_woh, g_wol, bo, out, nullptr, nullptr, 0, 0, 1.0f,
              blockIdx.y * BM, blockIdx.x * BN, smem);
}

// ---------------------------------------------------------------------------
// fp16x2 flash attention (log2-domain softmax; Q pre-scaled by .125*log2e)
// S = Qh*(Kh+Kl); O = P*(Vh+Vl). CTA = 128 q-rows x (b,h), 8 warps.
// smem: Q 16K | 2 stages x (Kh|Kl|Vh|Vl 8K each) = 81920.
// ---------------------------------------------------------------------------
#define ATT_Q 0
#define ATT_STG0 16384
#define ATT_STG_B 32768
#define ATT_SMEM (16384 + 2 * ATT_STG_B)   // 81920

__global__ __launch_bounds__(256, 2) void attn_kernel(const float* __restrict__ gm)
{
    extern __shared__ __align__(16) char smem[];
    const uint32_t sb = s2u(smem);
    const int tid  = threadIdx.x;
    const int lane = tid & 31;
    const int w    = tid >> 5;
    const int h    = blockIdx.x;
    const int q0   = blockIdx.y * 128;
    const int b    = blockIdx.z;
    const int bh   = b * NHEAD + h;

    const __half* Qh = g_oqh + ((size_t)bh * SEQ + q0) * DHEAD;
    const __half* Kh = g_okh + (size_t)bh * SEQ * DHEAD;
    const __half* Kl = g_okl + (size_t)bh * SEQ * DHEAD;
    const __half* Vh = g_ovh + (size_t)bh * SEQ * DHEAD;
    const __half* Vl = g_ovl + (size_t)bh * SEQ * DHEAD;

#pragma unroll
    for (int i = 0; i < 4; i++) {
        const int c = tid + i * 256;      // 0..1023
        const int r = c >> 3, off = c & 7;
        cp16(sb + ATT_Q + swz((uint32_t)r * 128 + off * 16),
             Qh + (size_t)r * DHEAD + off * 8);
    }
    auto load_stage = [&](int kt, int s) {
        const int k0 = kt * 64;
        const uint32_t base = sb + ATT_STG0 + (uint32_t)s * ATT_STG_B;
#pragma unroll
        for (int i = 0; i < 2; i++) {
            const int c = tid + i * 256;
            const int r = c >> 3, off = c & 7;
            const uint32_t d = swz((uint32_t)r * 128 + off * 16);
            const size_t g = (size_t)(k0 + r) * DHEAD + off * 8;
            cp16(base + d,         Kh + g);
            cp16(base + 8192 + d,  Kl + g);
            cp16(base + 16384 + d, Vh + g);
            cp16(base + 24576 + d, Vl + g);
        }
    };
    load_stage(0, 0);
    asm volatile("cp.async.commit_group;" ::: "memory");
    load_stage(1, 1);
    asm volatile("cp.async.commit_group;" ::: "memory");
    asm volatile("cp.async.wait_group 1;" ::: "memory");
    __syncthreads();

    const int l8 = lane & 7, lg = lane >> 3;
    const int a_row_off = ((lg & 1) ? 8 : 0) + l8;
    const int a_col_off = (lg & 2) ? 8 : 0;
    const int b_row_off = ((lg >> 1) ? 8 : 0) + l8;
    const int b_col_off = (lg & 1) ? 8 : 0;

    uint32_t qfh[4][4];
    const uint32_t qrowbyte = (uint32_t)(w * 16 + a_row_off) * 128;
#pragma unroll
    for (int ks = 0; ks < 4; ks++)
        ldm_x4(qfh[ks], sb + ATT_Q + swz(qrowbyte + (ks * 16 + a_col_off) * 2));

    float accv[8][4];
#pragma unroll
    for (int i = 0; i < 8; i++)
#pragma unroll
        for (int j = 0; j < 4; j++) accv[i][j] = 0.0f;
    float m0 = -INFINITY, m1 = -INFINITY, l0 = 0.0f, l1 = 0.0f;

    const int r0 = lane >> 2;
    const int qrow0 = q0 + w * 16 + r0;
    const float* gmRow0 = gm + ((size_t)b * SEQ + qrow0) * SEQ;
    const float* gmRow1 = gmRow0 + 8 * SEQ;
    const int colq = (lane & 3) * 2;

    for (int kt = 0; kt < SEQ / 64; kt++) {
        const int st = kt & 1;
        const uint32_t stg = sb + ATT_STG0 + (uint32_t)st * ATT_STG_B;

        // ---- S = Qh (Kh + Kl)^T ----
        float s[8][4];
#pragma unroll
        for (int i = 0; i < 8; i++)
#pragma unroll
            for (int j = 0; j < 4; j++) s[i][j] = 0.0f;
#pragma unroll
        for (int ks = 0; ks < 4; ks++) {
#pragma unroll
            for (int g16 = 0; g16 < 4; g16++) {
                const int row = g16 * 16 + b_row_off;
                const int col = ks * 16 + b_col_off;
                const uint32_t d = swz((uint32_t)row * 128 + col * 2);
                uint32_t kh4[4], kl4[4];
                ldm_x4(kh4, stg + d);
                ldm_x4(kl4, stg + 8192 + d);
                uint32_t bh0[2] = {kh4[0], kh4[1]}, bh1[2] = {kh4[2], kh4[3]};
                uint32_t bl0[2] = {kl4[0], kl4[1]}, bl1[2] = {kl4[2], kl4[3]};
                mma_f16(s[g16 * 2],     qfh[ks], bh0);
                mma_f16(s[g16 * 2],     qfh[ks], bl0);
                mma_f16(s[g16 * 2 + 1], qfh[ks], bh1);
                mma_f16(s[g16 * 2 + 1], qfh[ks], bl1);
            }
        }

        // ---- online softmax (log2 domain) + group weighting ----
        float rm0 = -INFINITY, rm1 = -INFINITY;
#pragma unroll
        for (int nt = 0; nt < 8; nt++) {
            rm0 = fmaxf(rm0, fmaxf(s[nt][0], s[nt][1]));
            rm1 = fmaxf(rm1, fmaxf(s[nt][2], s[nt][3]));
        }
        rm0 = fmaxf(rm0, __shfl_xor_sync(0xffffffffu, rm0, 1));
        rm0 = fmaxf(rm0, __shfl_xor_sync(0xffffffffu, rm0, 2));
        rm1 = fmaxf(rm1, __shfl_xor_sync(0xffffffffu, rm1, 1));
        rm1 = fmaxf(rm1, __shfl_xor_sync(0xffffffffu, rm1, 2));
        const float m0n = fmaxf(m0, rm0);
        const float m1n = fmaxf(m1, rm1);
        const float c0 = ex2(m0 - m0n);
        const float c1 = ex2(m1 - m1n);
        l0 *= c0; l1 *= c1;
        m0 = m0n; m1 = m1n;
#pragma unroll
        for (int nt = 0; nt < 8; nt++) {
            accv[nt][0] *= c0; accv[nt][1] *= c0;
            accv[nt][2] *= c1; accv[nt][3] *= c1;
        }

        // P (already * group) packed to single fp16 a-frags
        uint32_t aP[4][4];
        const int kbase = kt * 64 + colq;
#pragma unroll
        for (int nt = 0; nt < 8; nt++) {
            const int kc = kbase + nt * 8;
            const float2 g0 = *(const float2*)(gmRow0 + kc);
            const float2 g1 = *(const float2*)(gmRow1 + kc);
            const float p00 = ex2(s[nt][0] - m0);
            const float p01 = ex2(s[nt][1] - m0);
            const float p10 = ex2(s[nt][2] - m1);
            const float p11 = ex2(s[nt][3] - m1);
            l0 += (g0.x >= 0.0f ? p00 : 0.0f) + (g0.y >= 0.0f ? p01 : 0.0f);
            l1 += (g1.x >= 0.0f ? p10 : 0.0f) + (g1.y >= 0.0f ? p11 : 0.0f);
            const int ks = nt >> 1, half = (nt & 1) * 2;
            aP[ks][half + 0] = pack_h2(p00 * fmaxf(g0.x, 0.0f), p01 * fmaxf(g0.y, 0.0f));
            aP[ks][half + 1] = pack_h2(p10 * fmaxf(g1.x, 0.0f), p11 * fmaxf(g1.y, 0.0f));
        }

        // ---- acc += P (Vh + Vl) ----
#pragma unroll
        for (int ks = 0; ks < 4; ks++) {
#pragma unroll
            for (int ng = 0; ng < 4; ng++) {
                const int row = ks * 16 + ((lg & 1) ? 8 : 0) + l8;
                const int col = ng * 16 + ((lg >> 1) ? 8 : 0);
                const uint32_t d = swz((uint32_t)row * 128 + col * 2);
                uint32_t vh4[4], vl4[4];
                ldm_x4_t(vh4, stg + 16384 + d);
                ldm_x4_t(vl4, stg + 24576 + d);
                uint32_t bh0[2] = {vh4[0], vh4[1]}, bh1[2] = {vh4[2], vh4[3]};
                uint32_t bl0[2] = {vl4[0], vl4[1]}, bl1[2] = {vl4[2], vl4[3]};
                mma_f16(accv[ng * 2],     aP[ks], bh0);
                mma_f16(accv[ng * 2],     aP[ks], bl0);
                mma_f16(accv[ng * 2 + 1], aP[ks], bh1);
                mma_f16(accv[ng * 2 + 1], aP[ks], bl1);
            }
        }

        __syncthreads();
        if (kt + 2 < SEQ / 64) load_stage(kt + 2, st);
        asm volatile("cp.async.commit_group;" ::: "memory");
        if (kt + 1 < SEQ / 64) {
            asm volatile("cp.async.wait_group 1;" ::: "memory");
            __syncthreads();
        }
    }

    l0 += __shfl_xor_sync(0xffffffffu, l0, 1);
    l0 += __shfl_xor_sync(0xffffffffu, l0, 2);
    l1 += __shfl_xor_sync(0xffffffffu, l1, 1);
    l1 += __shfl_xor_sync(0xffffffffu, l1, 2);
    const float inv0 = 1.0f / l0, inv1 = 1.0f / l1;

    const size_t tok0 = (size_t)b * SEQ + qrow0;
    __half* ch0 = g_ch + tok0 * DMODEL + h * DHEAD + colq;
#pragma unroll
    for (int nt = 0; nt < 8; nt++) {
        *(uint32_t*)(ch0 + nt * 8) = pack_h2(accv[nt][0] * inv0, accv[nt][1] * inv0);
        *(uint32_t*)(ch0 + 8 * DMODEL + nt * 8) =
            pack_h2(accv[nt][2] * inv1, accv[nt][3] * inv1);
    }
}

// ---------------------------------------------------------------------------
extern "C" void kernel_launch(void* const* d_in, const int* in_sizes, int n_in,
                              void* d_out, int out_size)
{
    (void)in_sizes; (void)n_in; (void)out_size;
    const float* query = (const float*)d_in[0];
    const float* key_  = (const float*)d_in[1];
    const float* value = (const float*)d_in[2];
    const int*   mask  = (const int*)  d_in[3];
    const float* group = (const float*)d_in[4];
    const float* bq = (const float*)d_in[6];
    const float* bk = (const float*)d_in[8];
    const float* bv = (const float*)d_in[10];
    const float* bo = (const float*)d_in[12];
    float* out = (float*)d_out;

    float* gmp;
    cudaGetSymbolAddress((void**)&gmp, g_gm);

    cudaFuncSetAttribute(gemm_qkv_kernel, cudaFuncAttributeMaxDynamicSharedMemorySize,
                         GEMM_SMEM);
    cudaFuncSetAttribute(gemm_out_kernel, cudaFuncAttributeMaxDynamicSharedMemorySize,
                         GEMM_SMEM);
    cudaFuncSetAttribute(attn_kernel, cudaFuncAttributeMaxDynamicSharedMemorySize,
                         ATT_SMEM);

    cvt_act_kernel<<<dim3(NTOK * (DMODEL / 8) / 256, 3), 256>>>(query, key_, value);
    cvt_w_kernel<<<dim3(DMODEL * (DMODEL / 8) / 256, 4), 256>>>(
        (const float*)d_in[5], (const float*)d_in[7],
        (const float*)d_in[9], (const float*)d_in[11]);
    prep_gm_kernel<<<BATCH * SEQ * SEQ / 4 / 256, 256>>>(mask, group, gmp);

    const float QSCALE = 0.125f * 1.44269504088896f;  // 1/sqrt(DK) * log2(e)
    gemm_qkv_kernel<<<dim3(DMODEL / BN, NTOK / BM, 3), GEMM_THREADS, GEMM_SMEM>>>(
        bq, bk, bv, QSCALE);

    attn_kernel<<<dim3(NHEAD, SEQ / 128, BATCH), 256, ATT_SMEM>>>(gmp);

    gemm_out_kernel<<<dim3(DMODEL / BN, NTOK / BM), GEMM_THREADS, GEMM_SMEM>>>(bo, out);
}

// round 10
// speedup vs baseline: 1.4747x; 1.1403x over previous
#include <cuda_runtime.h>
#include <cuda_fp16.h>
#include <math.h>
#include <stdint.h>

#define BATCH  4
#define SEQ    1024
#define DMODEL 1024
#define NHEAD  16
#define DHEAD  64
#define NTOK   (BATCH * SEQ)

// ---------------- scratch (device globals; no runtime alloc) ----------------
// activations: fp16 hi only (2-pass scheme corrects the weight side)
__device__ __half g_qa[NTOK * DMODEL], g_ka[NTOK * DMODEL], g_va[NTOK * DMODEL];
// weights: fp16 hi + lo
__device__ __half g_wqh[DMODEL * DMODEL], g_wql[DMODEL * DMODEL];
__device__ __half g_wkh[DMODEL * DMODEL], g_wkl[DMODEL * DMODEL];
__device__ __half g_wvh[DMODEL * DMODEL], g_wvl[DMODEL * DMODEL];
__device__ __half g_woh[DMODEL * DMODEL], g_wol[DMODEL * DMODEL];
// projected Q/K/V, fp16 hi only, [b,h,s,64] layout (Q pre-scaled by .125*log2e)
__device__ __half g_oqh[NTOK * DMODEL];
__device__ __half g_okh[NTOK * DMODEL];
__device__ __half g_ovh[NTOK * DMODEL];
// attention context, fp16 hi only, row-major [tok][1024]
__device__ __half g_ch[NTOK * DMODEL];
// fused mask*group: allowed ? group : -1
__device__ float g_gm[BATCH * SEQ * SEQ];

// ---------------------------------------------------------------------------
// shared PTX helpers
// ---------------------------------------------------------------------------
__device__ __forceinline__ uint32_t s2u(const void* p) {
    uint32_t a;
    asm("{ .reg .u64 t; cvta.to.shared.u64 t, %1; cvt.u32.u64 %0, t; }"
        : "=r"(a) : "l"(p));
    return a;
}
__device__ __forceinline__ void cp16(uint32_t dst, const void* src) {
    asm volatile("cp.async.cg.shared.global [%0], [%1], 16;" :: "r"(dst), "l"(src));
}
__device__ __forceinline__ void ldm_x4(uint32_t* r, uint32_t addr) {
    asm volatile("ldmatrix.sync.aligned.m8n8.x4.shared.b16 {%0,%1,%2,%3}, [%4];"
                 : "=r"(r[0]), "=r"(r[1]), "=r"(r[2]), "=r"(r[3]) : "r"(addr));
}
__device__ __forceinline__ void ldm_x4_t(uint32_t* r, uint32_t addr) {
    asm volatile("ldmatrix.sync.aligned.m8n8.x4.trans.shared.b16 {%0,%1,%2,%3}, [%4];"
                 : "=r"(r[0]), "=r"(r[1]), "=r"(r[2]), "=r"(r[3]) : "r"(addr));
}
__device__ __forceinline__ void mma_f16(float* c, const uint32_t* a,
                                        const uint32_t* b) {
    asm volatile(
        "mma.sync.aligned.m16n8k16.row.col.f32.f16.f16.f32 "
        "{%0,%1,%2,%3}, {%4,%5,%6,%7}, {%8,%9}, {%0,%1,%2,%3};"
        : "+f"(c[0]), "+f"(c[1]), "+f"(c[2]), "+f"(c[3])
        : "r"(a[0]), "r"(a[1]), "r"(a[2]), "r"(a[3]), "r"(b[0]), "r"(b[1]));
}
__device__ __forceinline__ uint32_t swz(uint32_t byte) {
    return byte ^ ((byte >> 3) & 0x70);
}
__device__ __forceinline__ uint32_t pack_h2(float x, float y) {
    uint32_t r;
    asm("cvt.rn.f16x2.f32 %0, %1, %2;" : "=r"(r) : "f"(y), "f"(x));
    return r;
}
__device__ __forceinline__ void split2h(float x, float y, uint32_t& hi, uint32_t& lo) {
    hi = pack_h2(x, y);
    const __half2 h = *(const __half2*)&hi;
    const float2 f = __half22float2(h);
    lo = pack_h2(x - f.x, y - f.y);
}
__device__ __forceinline__ float ex2(float x) {
    float r;
    asm("ex2.approx.f32 %0, %1;" : "=f"(r) : "f"(x));
    return r;
}

// ---------------------------------------------------------------------------
// conversions
// ---------------------------------------------------------------------------
__global__ __launch_bounds__(256) void cvt_act_kernel(
    const float* __restrict__ s0, const float* __restrict__ s1,
    const float* __restrict__ s2)
{
    const int t = blockIdx.x * 256 + threadIdx.x;
    if (t >= NTOK * (DMODEL / 8)) return;
    const int z = blockIdx.y;
    const float* src = (z == 0) ? s0 : (z == 1) ? s1 : s2;
    __half* dst = (z == 0) ? g_qa : (z == 1) ? g_ka : g_va;
    const int idx = t * 8;
    const float4 a = *(const float4*)(src + idx);
    const float4 b = *(const float4*)(src + idx + 4);
    uint4 o;
    o.x = pack_h2(a.x, a.y);
    o.y = pack_h2(a.z, a.w);
    o.z = pack_h2(b.x, b.y);
    o.w = pack_h2(b.z, b.w);
    *(uint4*)(dst + idx) = o;
}

__global__ __launch_bounds__(256) void cvt_w_kernel(
    const float* __restrict__ s0, const float* __restrict__ s1,
    const float* __restrict__ s2, const float* __restrict__ s3)
{
    const int t = blockIdx.x * 256 + threadIdx.x;
    if (t >= DMODEL * (DMODEL / 8)) return;
    const int z = blockIdx.y;
    const float* src = (z == 0) ? s0 : (z == 1) ? s1 : (z == 2) ? s2 : s3;
    __half* hi = (z == 0) ? g_wqh : (z == 1) ? g_wkh : (z == 2) ? g_wvh : g_woh;
    __half* lo = (z == 0) ? g_wql : (z == 1) ? g_wkl : (z == 2) ? g_wvl : g_wol;
    const int idx = t * 8;
    const float4 a = *(const float4*)(src + idx);
    const float4 b = *(const float4*)(src + idx + 4);
    const float f[8] = {a.x, a.y, a.z, a.w, b.x, b.y, b.z, b.w};
    uint4 oh, ol;
    split2h(f[0], f[1], oh.x, ol.x);
    split2h(f[2], f[3], oh.y, ol.y);
    split2h(f[4], f[5], oh.z, ol.z);
    split2h(f[6], f[7], oh.w, ol.w);
    *(uint4*)(hi + idx) = oh;
    *(uint4*)(lo + idx) = ol;
}

__global__ __launch_bounds__(256) void prep_gm_kernel(
    const int* __restrict__ mask, const float* __restrict__ group,
    float* __restrict__ gm)
{
    const int t = blockIdx.x * 256 + threadIdx.x;
    if (t >= BATCH * SEQ * SEQ / 4) return;
    const int i = t * 4;
    const int q = (i >> 10) & 1023;
    const int k = i & 1023;
    const int4   mk = *(const int4*)(mask + i);
    const float4 gr = *(const float4*)(group + i);
    float4 o;
    o.x = (mk.x || q == k + 0) ? gr.x : -1.0f;
    o.y = (mk.y || q == k + 1) ? gr.y : -1.0f;
    o.z = (mk.z || q == k + 2) ? gr.z : -1.0f;
    o.w = (mk.w || q == k + 3) ? gr.w : -1.0f;
    *(float4*)(gm + i) = o;
}

// ---------------------------------------------------------------------------
// fp16x2 GEMM: out[r,c] = sum_k A[r,k] * (Wh[c,k]+Wl[c,k]) + bias[c]
// CTA tile 128x256, BK=64, 2 stages, 512 threads (16 warps, 32x64 warp tile).
// ---------------------------------------------------------------------------
#define GEMM_THREADS 512
#define BM 128
#define BN 256
#define BK 64
#define KTILES (DMODEL / BK)          // 16
#define PAD_B 144
#define TILE_AB (128 * PAD_B)         // 18432
#define TILE_BB (256 * PAD_B)         // 36864
#define OFF_BH  TILE_AB
#define STAGE_B (TILE_AB + 2 * TILE_BB)   // 92160
#define GEMM_SMEM (2 * STAGE_B)           // 184320

__device__ __forceinline__ void gemm_body(
    const __half* __restrict__ aH,
    const __half* __restrict__ bH, const __half* __restrict__ bL,
    const float* __restrict__ bias, float* __restrict__ outF,
    __half* __restrict__ outH,
    int mode, float oscale, int brow, int bcol, char* smem)
{
    const uint32_t sb = s2u(smem);
    const int tid  = threadIdx.x;
    const int lane = tid & 31;
    const int wid  = tid >> 5;
    const int warpM = wid >> 2;          // 0..3
    const int warpN = wid & 3;           // 0..3

    float acc[2][8][4];
#pragma unroll
    for (int i = 0; i < 2; i++)
#pragma unroll
        for (int j = 0; j < 8; j++)
#pragma unroll
            for (int k = 0; k < 4; k++) acc[i][j][k] = 0.0f;

    auto load_stage = [&](int kb, int s) {
        const int k0 = kb * BK;
        const uint32_t base = sb + (uint32_t)s * STAGE_B;
#pragma unroll
        for (int i = 0; i < 2; i++) {
            const int c = tid + i * GEMM_THREADS;   // 0..1023
            const int r = c >> 3;
            const int q = c & 7;
            cp16(base + (uint32_t)r * PAD_B + q * 16,
                 aH + (size_t)(brow + r) * DMODEL + k0 + q * 8);
        }
#pragma unroll
        for (int i = 0; i < 4; i++) {
            const int c = tid + i * GEMM_THREADS;   // 0..2047
            const int r = c >> 3;
            const int q = c & 7;
            const uint32_t dst = base + OFF_BH + (uint32_t)r * PAD_B + q * 16;
            const size_t boff = (size_t)(bcol + r) * DMODEL + k0 + q * 8;
            cp16(dst,           bH + boff);
            cp16(dst + TILE_BB, bL + boff);
        }
        asm volatile("cp.async.commit_group;" ::: "memory");
    };

    const int l8 = lane & 7, lg = lane >> 3;
    const int a_row_off = ((lg & 1) ? 8 : 0) + l8;
    const int a_col_off = (lg & 2) ? 8 : 0;
    const int b_row_off = ((lg >> 1) ? 8 : 0) + l8;
    const int b_col_off = (lg & 1) ? 8 : 0;

    load_stage(0, 0);
    load_stage(1, 1);
    asm volatile("cp.async.wait_group 1;" ::: "memory");
    __syncthreads();

    for (int kb = 0; kb < KTILES; kb++) {
        const uint32_t stg = sb + (uint32_t)(kb & 1) * STAGE_B;
#pragma unroll
        for (int ks = 0; ks < 4; ks++) {
            uint32_t ah[2][4];
#pragma unroll
            for (int mt = 0; mt < 2; mt++) {
                const int row = warpM * 32 + mt * 16 + a_row_off;
                const int col = ks * 16 + a_col_off;
                ldm_x4(ah[mt], stg + (uint32_t)row * PAD_B + col * 2);
            }
#pragma unroll
            for (int pt = 0; pt < 4; pt++) {
                const int n   = warpN * 64 + pt * 16 + b_row_off;
                const int col = ks * 16 + b_col_off;
                const uint32_t bd = stg + OFF_BH + (uint32_t)n * PAD_B + col * 2;
                uint32_t th[4], tl[4];
                ldm_x4(th, bd);
                ldm_x4(tl, bd + TILE_BB);
                uint32_t bh0[2] = {th[0], th[1]}, bh1[2] = {th[2], th[3]};
                uint32_t bl0[2] = {tl[0], tl[1]}, bl1[2] = {tl[2], tl[3]};
#pragma unroll
                for (int mt = 0; mt < 2; mt++) {
                    mma_f16(acc[mt][pt * 2],     ah[mt], bh0);
                    mma_f16(acc[mt][pt * 2],     ah[mt], bl0);
                    mma_f16(acc[mt][pt * 2 + 1], ah[mt], bh1);
                    mma_f16(acc[mt][pt * 2 + 1], ah[mt], bl1);
                }
            }
        }
        __syncthreads();
        if (kb + 2 < KTILES) load_stage(kb + 2, kb & 1);
        else asm volatile("cp.async.commit_group;" ::: "memory");
        if (kb + 1 < KTILES) {
            asm volatile("cp.async.wait_group 1;" ::: "memory");
            __syncthreads();
        }
    }

#pragma unroll
    for (int mt = 0; mt < 2; mt++) {
        const int row = brow + warpM * 32 + mt * 16 + (lane >> 2);
#pragma unroll
        for (int nt = 0; nt < 8; nt++) {
            const int col = bcol + warpN * 64 + (nt >> 1) * 16 + (nt & 1) * 8
                          + (lane & 3) * 2;
            const float b0 = bias[col], b1 = bias[col + 1];
            const float v00 = acc[mt][nt][0] + b0, v01 = acc[mt][nt][1] + b1;
            const float v10 = acc[mt][nt][2] + b0, v11 = acc[mt][nt][3] + b1;
            if (mode == 0) {
                *(float2*)(outF + (size_t)row * DMODEL + col) = make_float2(v00, v01);
                *(float2*)(outF + (size_t)(row + 8) * DMODEL + col) = make_float2(v10, v11);
            } else {
                const int h = col >> 6, dk = col & 63;
                const int bi = row >> 10, s = row & 1023;
                const size_t d0 = (((size_t)(bi * NHEAD + h)) * SEQ + s) * DHEAD + dk;
                *(uint32_t*)(outH + d0) = pack_h2(v00 * oscale, v01 * oscale);
                *(uint32_t*)(outH + d0 + 8 * DHEAD) = pack_h2(v10 * oscale, v11 * oscale);
            }
        }
    }
}

__global__ __launch_bounds__(GEMM_THREADS, 1) void gemm_qkv_kernel(
    const float* __restrict__ bq, const float* __restrict__ bk,
    const float* __restrict__ bv, float qscale)
{
    extern __shared__ __align__(16) char smem[];
    const int z = blockIdx.z;
    const __half *aH, *bH, *bL;
    __half *oH;
    const float* bias;
    float sc;
    if (z == 0)      { aH = g_qa; bH = g_wqh; bL = g_wql;
                       oH = g_oqh; bias = bq; sc = qscale; }
    else if (z == 1) { aH = g_ka; bH = g_wkh; bL = g_wkl;
                       oH = g_okh; bias = bk; sc = 1.0f; }
    else             { aH = g_va; bH = g_wvh; bL = g_wvl;
                       oH = g_ovh; bias = bv; sc = 1.0f; }
    gemm_body(aH, bH, bL, bias, nullptr, oH, 1, sc,
              blockIdx.y * BM, blockIdx.x * BN, smem);
}

__global__ __launch_bounds__(GEMM_THREADS, 1) void gemm_out_kernel(
    const float* __restrict__ bo, float* __restrict__ out)
{
    extern __shared__ __align__(16) char smem[];
    gemm_body(g_ch, g_woh, g_wol, bo, out, nullptr, 0, 1.0f,
              blockIdx.y * BM, blockIdx.x * BN, smem);
}

// ---------------------------------------------------------------------------
// Single-pass fp16 flash attention (log2-domain softmax; Q pre-scaled).
// S = Qh*Kh; O = P*Vh. CTA = 128 q-rows x (b,h), 8 warps, 64-key stages.
// smem: Q 16K | 2 stages x (Kh 8K | Vh 8K) = 49152.
// ---------------------------------------------------------------------------
#define ATT_Q 0
#define ATT_STG0 16384
#define ATT_STG_B 16384
#define ATT_SMEM (16384 + 2 * ATT_STG_B)   // 49152

__global__ __launch_bounds__(256, 2) void attn_kernel(const float* __restrict__ gm)
{
    extern __shared__ __align__(16) char smem[];
    const uint32_t sb = s2u(smem);
    const int tid  = threadIdx.x;
    const int lane = tid & 31;
    const int w    = tid >> 5;
    const int h    = blockIdx.x;
    const int q0   = blockIdx.y * 128;
    const int b    = blockIdx.z;
    const int bh   = b * NHEAD + h;

    const __half* Qh = g_oqh + ((size_t)bh * SEQ + q0) * DHEAD;
    const __half* Kh = g_okh + (size_t)bh * SEQ * DHEAD;
    const __half* Vh = g_ovh + (size_t)bh * SEQ * DHEAD;

#pragma unroll
    for (int i = 0; i < 4; i++) {
        const int c = tid + i * 256;      // 0..1023
        const int r = c >> 3, off = c & 7;
        cp16(sb + ATT_Q + swz((uint32_t)r * 128 + off * 16),
             Qh + (size_t)r * DHEAD + off * 8);
    }
    auto load_stage = [&](int kt, int s) {
        const int k0 = kt * 64;
        const uint32_t base = sb + ATT_STG0 + (uint32_t)s * ATT_STG_B;
#pragma unroll
        for (int i = 0; i < 2; i++) {
            const int c = tid + i * 256;  // 0..511
            const int r = c >> 3, off = c & 7;
            const uint32_t d = swz((uint32_t)r * 128 + off * 16);
            const size_t g = (size_t)(k0 + r) * DHEAD + off * 8;
            cp16(base + d,        Kh + g);
            cp16(base + 8192 + d, Vh + g);
        }
    };
    load_stage(0, 0);
    asm volatile("cp.async.commit_group;" ::: "memory");
    load_stage(1, 1);
    asm volatile("cp.async.commit_group;" ::: "memory");
    asm volatile("cp.async.wait_group 1;" ::: "memory");
    __syncthreads();

    const int l8 = lane & 7, lg = lane >> 3;
    const int a_row_off = ((lg & 1) ? 8 : 0) + l8;
    const int a_col_off = (lg & 2) ? 8 : 0;
    const int b_row_off = ((lg >> 1) ? 8 : 0) + l8;
    const int b_col_off = (lg & 1) ? 8 : 0;

    uint32_t qfh[4][4];
    const uint32_t qrowbyte = (uint32_t)(w * 16 + a_row_off) * 128;
#pragma unroll
    for (int ks = 0; ks < 4; ks++)
        ldm_x4(qfh[ks], sb + ATT_Q + swz(qrowbyte + (ks * 16 + a_col_off) * 2));

    float accv[8][4];
#pragma unroll
    for (int i = 0; i < 8; i++)
#pragma unroll
        for (int j = 0; j < 4; j++) accv[i][j] = 0.0f;
    float m0 = -INFINITY, m1 = -INFINITY, l0 = 0.0f, l1 = 0.0f;

    const int r0 = lane >> 2;
    const int qrow0 = q0 + w * 16 + r0;
    const float* gmRow0 = gm + ((size_t)b * SEQ + qrow0) * SEQ;
    const float* gmRow1 = gmRow0 + 8 * SEQ;
    const int colq = (lane & 3) * 2;

    for (int kt = 0; kt < SEQ / 64; kt++) {
        const int st = kt & 1;
        const uint32_t stg = sb + ATT_STG0 + (uint32_t)st * ATT_STG_B;

        // ---- S = Qh Kh^T (single pass) ----
        float s[8][4];
#pragma unroll
        for (int i = 0; i < 8; i++)
#pragma unroll
            for (int j = 0; j < 4; j++) s[i][j] = 0.0f;
#pragma unroll
        for (int ks = 0; ks < 4; ks++) {
#pragma unroll
            for (int g16 = 0; g16 < 4; g16++) {
                const int row = g16 * 16 + b_row_off;
                const int col = ks * 16 + b_col_off;
                uint32_t kh4[4];
                ldm_x4(kh4, stg + swz((uint32_t)row * 128 + col * 2));
                uint32_t bh0[2] = {kh4[0], kh4[1]}, bh1[2] = {kh4[2], kh4[3]};
                mma_f16(s[g16 * 2],     qfh[ks], bh0);
                mma_f16(s[g16 * 2 + 1], qfh[ks], bh1);
            }
        }

        // ---- online softmax (log2 domain) + group weighting ----
        float rm0 = -INFINITY, rm1 = -INFINITY;
#pragma unroll
        for (int nt = 0; nt < 8; nt++) {
            rm0 = fmaxf(rm0, fmaxf(s[nt][0], s[nt][1]));
            rm1 = fmaxf(rm1, fmaxf(s[nt][2], s[nt][3]));
        }
        rm0 = fmaxf(rm0, __shfl_xor_sync(0xffffffffu, rm0, 1));
        rm0 = fmaxf(rm0, __shfl_xor_sync(0xffffffffu, rm0, 2));
        rm1 = fmaxf(rm1, __shfl_xor_sync(0xffffffffu, rm1, 1));
        rm1 = fmaxf(rm1, __shfl_xor_sync(0xffffffffu, rm1, 2));
        const float m0n = fmaxf(m0, rm0);
        const float m1n = fmaxf(m1, rm1);
        const float c0 = ex2(m0 - m0n);
        const float c1 = ex2(m1 - m1n);
        l0 *= c0; l1 *= c1;
        m0 = m0n; m1 = m1n;
#pragma unroll
        for (int nt = 0; nt < 8; nt++) {
            accv[nt][0] *= c0; accv[nt][1] *= c0;
            accv[nt][2] *= c1; accv[nt][3] *= c1;
        }

        // P (already * group) packed to single fp16 a-frags
        uint32_t aP[4][4];
        const int kbase = kt * 64 + colq;
#pragma unroll
        for (int nt = 0; nt < 8; nt++) {
            const int kc = kbase + nt * 8;
            const float2 g0 = *(const float2*)(gmRow0 + kc);
            const float2 g1 = *(const float2*)(gmRow1 + kc);
            const float p00 = ex2(s[nt][0] - m0);
            const float p01 = ex2(s[nt][1] - m0);
            const float p10 = ex2(s[nt][2] - m1);
            const float p11 = ex2(s[nt][3] - m1);
            l0 += (g0.x >= 0.0f ? p00 : 0.0f) + (g0.y >= 0.0f ? p01 : 0.0f);
            l1 += (g1.x >= 0.0f ? p10 : 0.0f) + (g1.y >= 0.0f ? p11 : 0.0f);
            const int ks = nt >> 1, half = (nt & 1) * 2;
            aP[ks][half + 0] = pack_h2(p00 * fmaxf(g0.x, 0.0f), p01 * fmaxf(g0.y, 0.0f));
            aP[ks][half + 1] = pack_h2(p10 * fmaxf(g1.x, 0.0f), p11 * fmaxf(g1.y, 0.0f));
        }

        // ---- acc += P Vh (single pass) ----
#pragma unroll
        for (int ks = 0; ks < 4; ks++) {
#pragma unroll
            for (int ng = 0; ng < 4; ng++) {
                const int row = ks * 16 + ((lg & 1) ? 8 : 0) + l8;
                const int col = ng * 16 + ((lg >> 1) ? 8 : 0);
                uint32_t vh4[4];
                ldm_x4_t(vh4, stg + 8192 + swz((uint32_t)row * 128 + col * 2));
                uint32_t bh0[2] = {vh4[0], vh4[1]}, bh1[2] = {vh4[2], vh4[3]};
                mma_f16(accv[ng * 2],     aP[ks], bh0);
                mma_f16(accv[ng * 2 + 1], aP[ks], bh1);
            }
        }

        __syncthreads();
        if (kt + 2 < SEQ / 64) load_stage(kt + 2, st);
        asm volatile("cp.async.commit_group;" ::: "memory");
        if (kt + 1 < SEQ / 64) {
            asm volatile("cp.async.wait_group 1;" ::: "memory");
            __syncthreads();
        }
    }

    l0 += __shfl_xor_sync(0xffffffffu, l0, 1);
    l0 += __shfl_xor_sync(0xffffffffu, l0, 2);
    l1 += __shfl_xor_sync(0xffffffffu, l1, 1);
    l1 += __shfl_xor_sync(0xffffffffu, l1, 2);
    const float inv0 = 1.0f / l0, inv1 = 1.0f / l1;

    const size_t tok0 = (size_t)b * SEQ + qrow0;
    __half* ch0 = g_ch + tok0 * DMODEL + h * DHEAD + colq;
#pragma unroll
    for (int nt = 0; nt < 8; nt++) {
        *(uint32_t*)(ch0 + nt * 8) = pack_h2(accv[nt][0] * inv0, accv[nt][1] * inv0);
        *(uint32_t*)(ch0 + 8 * DMODEL + nt * 8) =
            pack_h2(accv[nt][2] * inv1, accv[nt][3] * inv1);
    }
}

// ---------------------------------------------------------------------------
extern "C" void kernel_launch(void* const* d_in, const int* in_sizes, int n_in,
                              void* d_out, int out_size)
{
    (void)in_sizes; (void)n_in; (void)out_size;
    const float* query = (const float*)d_in[0];
    const float* key_  = (const float*)d_in[1];
    const float* value = (const float*)d_in[2];
    const int*   mask  = (const int*)  d_in[3];
    const float* group = (const float*)d_in[4];
    const float* bq = (const float*)d_in[6];
    const float* bk = (const float*)d_in[8];
    const float* bv = (const float*)d_in[10];
    const float* bo = (const float*)d_in[12];
    float* out = (float*)d_out;

    float* gmp;
    cudaGetSymbolAddress((void**)&gmp, g_gm);

    cudaFuncSetAttribute(gemm_qkv_kernel, cudaFuncAttributeMaxDynamicSharedMemorySize,
                         GEMM_SMEM);
    cudaFuncSetAttribute(gemm_out_kernel, cudaFuncAttributeMaxDynamicSharedMemorySize,
                         GEMM_SMEM);
    cudaFuncSetAttribute(attn_kernel, cudaFuncAttributeMaxDynamicSharedMemorySize,
                         ATT_SMEM);

    cvt_act_kernel<<<dim3(NTOK * (DMODEL / 8) / 256, 3), 256>>>(query, key_, value);
    cvt_w_kernel<<<dim3(DMODEL * (DMODEL / 8) / 256, 4), 256>>>(
        (const float*)d_in[5], (const float*)d_in[7],
        (const float*)d_in[9], (const float*)d_in[11]);
    prep_gm_kernel<<<BATCH * SEQ * SEQ / 4 / 256, 256>>>(mask, group, gmp);

    const float QSCALE = 0.125f * 1.44269504088896f;  // 1/sqrt(DK) * log2(e)
    gemm_qkv_kernel<<<dim3(DMODEL / BN, NTOK / BM, 3), GEMM_THREADS, GEMM_SMEM>>>(
        bq, bk, bv, QSCALE);

    attn_kernel<<<dim3(NHEAD, SEQ / 128, BATCH), 256, ATT_SMEM>>>(gmp);

    gemm_out_kernel<<<dim3(DMODEL / BN, NTOK / BM), GEMM_THREADS, GEMM_SMEM>>>(bo, out);
}

// round 11
// speedup vs baseline: 2.0468x; 1.3879x over previous
#include <cuda_runtime.h>
#include <cuda_fp16.h>
#include <math.h>
#include <stdint.h>

#define BATCH  4
#define SEQ    1024
#define DMODEL 1024
#define NHEAD  16
#define DHEAD  64
#define NTOK   (BATCH * SEQ)

// ---------------- scratch (device globals; no runtime alloc) ----------------
// activations + weights: fp16 single-rounded
__device__ __half g_qa[NTOK * DMODEL], g_ka[NTOK * DMODEL], g_va[NTOK * DMODEL];
__device__ __half g_wq[DMODEL * DMODEL], g_wk[DMODEL * DMODEL];
__device__ __half g_wv[DMODEL * DMODEL], g_wo[DMODEL * DMODEL];
// projected Q/K/V, fp16, [b,h,s,64] layout (Q pre-scaled by .125*log2e)
__device__ __half g_oqh[NTOK * DMODEL];
__device__ __half g_okh[NTOK * DMODEL];
__device__ __half g_ovh[NTOK * DMODEL];
// attention context, fp16, row-major [tok][1024]
__device__ __half g_ch[NTOK * DMODEL];
// fused mask*group: allowed ? group : -1
__device__ float g_gm[BATCH * SEQ * SEQ];

// ---------------------------------------------------------------------------
// shared PTX helpers
// ---------------------------------------------------------------------------
__device__ __forceinline__ uint32_t s2u(const void* p) {
    uint32_t a;
    asm("{ .reg .u64 t; cvta.to.shared.u64 t, %1; cvt.u32.u64 %0, t; }"
        : "=r"(a) : "l"(p));
    return a;
}
__device__ __forceinline__ void cp16(uint32_t dst, const void* src) {
    asm volatile("cp.async.cg.shared.global [%0], [%1], 16;" :: "r"(dst), "l"(src));
}
__device__ __forceinline__ void ldm_x4(uint32_t* r, uint32_t addr) {
    asm volatile("ldmatrix.sync.aligned.m8n8.x4.shared.b16 {%0,%1,%2,%3}, [%4];"
                 : "=r"(r[0]), "=r"(r[1]), "=r"(r[2]), "=r"(r[3]) : "r"(addr));
}
__device__ __forceinline__ void ldm_x4_t(uint32_t* r, uint32_t addr) {
    asm volatile("ldmatrix.sync.aligned.m8n8.x4.trans.shared.b16 {%0,%1,%2,%3}, [%4];"
                 : "=r"(r[0]), "=r"(r[1]), "=r"(r[2]), "=r"(r[3]) : "r"(addr));
}
__device__ __forceinline__ void mma_f16(float* c, const uint32_t* a,
                                        const uint32_t* b) {
    asm volatile(
        "mma.sync.aligned.m16n8k16.row.col.f32.f16.f16.f32 "
        "{%0,%1,%2,%3}, {%4,%5,%6,%7}, {%8,%9}, {%0,%1,%2,%3};"
        : "+f"(c[0]), "+f"(c[1]), "+f"(c[2]), "+f"(c[3])
        : "r"(a[0]), "r"(a[1]), "r"(a[2]), "r"(a[3]), "r"(b[0]), "r"(b[1]));
}
__device__ __forceinline__ uint32_t swz(uint32_t byte) {
    return byte ^ ((byte >> 3) & 0x70);
}
__device__ __forceinline__ uint32_t pack_h2(float x, float y) {
    uint32_t r;
    asm("cvt.rn.f16x2.f32 %0, %1, %2;" : "=r"(r) : "f"(y), "f"(x));
    return r;
}
__device__ __forceinline__ float ex2(float x) {
    float r;
    asm("ex2.approx.f32 %0, %1;" : "=f"(r) : "f"(x));
    return r;
}

// ---------------------------------------------------------------------------
// conversions (fp32 -> fp16, plain)
// ---------------------------------------------------------------------------
// z=0..2: query/key/value activations; z=3..6: Wq/Wk/Wv/Wo
__global__ __launch_bounds__(256) void cvt_kernel(
    const float* __restrict__ s0, const float* __restrict__ s1,
    const float* __restrict__ s2, const float* __restrict__ s3,
    const float* __restrict__ s4, const float* __restrict__ s5,
    const float* __restrict__ s6)
{
    const int z = blockIdx.y;
    const int n8 = (z < 3) ? NTOK * (DMODEL / 8) : DMODEL * (DMODEL / 8);
    const int t = blockIdx.x * 256 + threadIdx.x;
    if (t >= n8) return;
    const float* src;
    __half* dst;
    switch (z) {
        case 0: src = s0; dst = g_qa; break;
        case 1: src = s1; dst = g_ka; break;
        case 2: src = s2; dst = g_va; break;
        case 3: src = s3; dst = g_wq; break;
        case 4: src = s4; dst = g_wk; break;
        case 5: src = s5; dst = g_wv; break;
        default: src = s6; dst = g_wo; break;
    }
    const int idx = t * 8;
    const float4 a = *(const float4*)(src + idx);
    const float4 b = *(const float4*)(src + idx + 4);
    uint4 o;
    o.x = pack_h2(a.x, a.y);
    o.y = pack_h2(a.z, a.w);
    o.z = pack_h2(b.x, b.y);
    o.w = pack_h2(b.z, b.w);
    *(uint4*)(dst + idx) = o;
}

// gm = (mask || q==k) ? group : -1
__global__ __launch_bounds__(256) void prep_gm_kernel(
    const int* __restrict__ mask, const float* __restrict__ group,
    float* __restrict__ gm)
{
    const int t = blockIdx.x * 256 + threadIdx.x;
    if (t >= BATCH * SEQ * SEQ / 4) return;
    const int i = t * 4;
    const int q = (i >> 10) & 1023;
    const int k = i & 1023;
    const int4   mk = *(const int4*)(mask + i);
    const float4 gr = *(const float4*)(group + i);
    float4 o;
    o.x = (mk.x || q == k + 0) ? gr.x : -1.0f;
    o.y = (mk.y || q == k + 1) ? gr.y : -1.0f;
    o.z = (mk.z || q == k + 2) ? gr.z : -1.0f;
    o.w = (mk.w || q == k + 3) ? gr.w : -1.0f;
    *(float4*)(gm + i) = o;
}

// ---------------------------------------------------------------------------
// fp16 GEMM: out[r,c] = sum_k A[r,k] * W[c,k] + bias[c]
// CTA tile 128x256, BK=64, 3 stages, 512 threads (16 warps, 32x64 warp tile).
// ---------------------------------------------------------------------------
#define GEMM_THREADS 512
#define BM 128
#define BN 256
#define BK 64
#define STAGES 3
#define KTILES (DMODEL / BK)          // 16
#define PAD_B 144
#define TILE_AB (128 * PAD_B)         // 18432
#define TILE_BB (256 * PAD_B)         // 36864
#define OFF_BH  TILE_AB
#define STAGE_B (TILE_AB + TILE_BB)       // 55296
#define GEMM_SMEM (STAGES * STAGE_B)      // 165888

__device__ __forceinline__ void gemm_body(
    const __half* __restrict__ aH, const __half* __restrict__ bH,
    const float* __restrict__ bias, float* __restrict__ outF,
    __half* __restrict__ outH,
    int mode, float oscale, int brow, int bcol, char* smem)
{
    const uint32_t sb = s2u(smem);
    const int tid  = threadIdx.x;
    const int lane = tid & 31;
    const int wid  = tid >> 5;
    const int warpM = wid >> 2;          // 0..3
    const int warpN = wid & 3;           // 0..3

    float acc[2][8][4];
#pragma unroll
    for (int i = 0; i < 2; i++)
#pragma unroll
        for (int j = 0; j < 8; j++)
#pragma unroll
            for (int k = 0; k < 4; k++) acc[i][j][k] = 0.0f;

    auto load_stage = [&](int kb, int s) {
        const int k0 = kb * BK;
        const uint32_t base = sb + (uint32_t)s * STAGE_B;
#pragma unroll
        for (int i = 0; i < 2; i++) {
            const int c = tid + i * GEMM_THREADS;   // 0..1023
            const int r = c >> 3;
            const int q = c & 7;
            cp16(base + (uint32_t)r * PAD_B + q * 16,
                 aH + (size_t)(brow + r) * DMODEL + k0 + q * 8);
        }
#pragma unroll
        for (int i = 0; i < 4; i++) {
            const int c = tid + i * GEMM_THREADS;   // 0..2047
            const int r = c >> 3;
            const int q = c & 7;
            cp16(base + OFF_BH + (uint32_t)r * PAD_B + q * 16,
                 bH + (size_t)(bcol + r) * DMODEL + k0 + q * 8);
        }
        asm volatile("cp.async.commit_group;" ::: "memory");
    };

    const int l8 = lane & 7, lg = lane >> 3;
    const int a_row_off = ((lg & 1) ? 8 : 0) + l8;
    const int a_col_off = (lg & 2) ? 8 : 0;
    const int b_row_off = ((lg >> 1) ? 8 : 0) + l8;
    const int b_col_off = (lg & 1) ? 8 : 0;

    load_stage(0, 0);
    load_stage(1, 1);
    asm volatile("cp.async.wait_group 1;" ::: "memory");
    __syncthreads();

    for (int kb = 0; kb < KTILES; kb++) {
        const uint32_t stg = sb + (uint32_t)(kb % STAGES) * STAGE_B;
#pragma unroll
        for (int ks = 0; ks < 4; ks++) {
            uint32_t ah[2][4];
#pragma unroll
            for (int mt = 0; mt < 2; mt++) {
                const int row = warpM * 32 + mt * 16 + a_row_off;
                const int col = ks * 16 + a_col_off;
                ldm_x4(ah[mt], stg + (uint32_t)row * PAD_B + col * 2);
            }
#pragma unroll
            for (int pt = 0; pt < 4; pt++) {
                const int n   = warpN * 64 + pt * 16 + b_row_off;
                const int col = ks * 16 + b_col_off;
                uint32_t th[4];
                ldm_x4(th, stg + OFF_BH + (uint32_t)n * PAD_B + col * 2);
                uint32_t bh0[2] = {th[0], th[1]}, bh1[2] = {th[2], th[3]};
#pragma unroll
                for (int mt = 0; mt < 2; mt++) {
                    mma_f16(acc[mt][pt * 2],     ah[mt], bh0);
                    mma_f16(acc[mt][pt * 2 + 1], ah[mt], bh1);
                }
            }
        }
        __syncthreads();  // all warps done reading stage (kb-1)'s buffer target
        if (kb + 2 < KTILES) load_stage(kb + 2, (kb + 2) % STAGES);
        else asm volatile("cp.async.commit_group;" ::: "memory");
        if (kb + 1 < KTILES) {
            asm volatile("cp.async.wait_group 1;" ::: "memory");
            __syncthreads();
        }
    }

#pragma unroll
    for (int mt = 0; mt < 2; mt++) {
        const int row = brow + warpM * 32 + mt * 16 + (lane >> 2);
#pragma unroll
        for (int nt = 0; nt < 8; nt++) {
            const int col = bcol + warpN * 64 + (nt >> 1) * 16 + (nt & 1) * 8
                          + (lane & 3) * 2;
            const float b0 = bias[col], b1 = bias[col + 1];
            const float v00 = acc[mt][nt][0] + b0, v01 = acc[mt][nt][1] + b1;
            const float v10 = acc[mt][nt][2] + b0, v11 = acc[mt][nt][3] + b1;
            if (mode == 0) {
                *(float2*)(outF + (size_t)row * DMODEL + col) = make_float2(v00, v01);
                *(float2*)(outF + (size_t)(row + 8) * DMODEL + col) = make_float2(v10, v11);
            } else {
                const int h = col >> 6, dk = col & 63;
                const int bi = row >> 10, s = row & 1023;
                const size_t d0 = (((size_t)(bi * NHEAD + h)) * SEQ + s) * DHEAD + dk;
                *(uint32_t*)(outH + d0) = pack_h2(v00 * oscale, v01 * oscale);
                *(uint32_t*)(outH + d0 + 8 * DHEAD) = pack_h2(v10 * oscale, v11 * oscale);
            }
        }
    }
}

__global__ __launch_bounds__(GEMM_THREADS, 1) void gemm_qkv_kernel(
    const float* __restrict__ bq, const float* __restrict__ bk,
    const float* __restrict__ bv, float qscale)
{
    extern __shared__ __align__(16) char smem[];
    const int z = blockIdx.z;
    const __half *aH, *bH;
    __half *oH;
    const float* bias;
    float sc;
    if (z == 0)      { aH = g_qa; bH = g_wq; oH = g_oqh; bias = bq; sc = qscale; }
    else if (z == 1) { aH = g_ka; bH = g_wk; oH = g_okh; bias = bk; sc = 1.0f; }
    else             { aH = g_va; bH = g_wv; oH = g_ovh; bias = bv; sc = 1.0f; }
    gemm_body(aH, bH, bias, nullptr, oH, 1, sc,
              blockIdx.y * BM, blockIdx.x * BN, smem);
}

__global__ __launch_bounds__(GEMM_THREADS, 1) void gemm_out_kernel(
    const float* __restrict__ bo, float* __restrict__ out)
{
    extern __shared__ __align__(16) char smem[];
    gemm_body(g_ch, g_wo, bo, out, nullptr, 0, 1.0f,
              blockIdx.y * BM, blockIdx.x * BN, smem);
}

// ---------------------------------------------------------------------------
// Single-pass fp16 flash attention (log2-domain softmax; Q pre-scaled).
// S = Qh*Kh; O = P*Vh. CTA = 128 q-rows x (b,h), 8 warps, 64-key stages.
// smem: Q 16K | 2 stages x (Kh 8K | Vh 8K) = 49152.
// ---------------------------------------------------------------------------
#define ATT_Q 0
#define ATT_STG0 16384
#define ATT_STG_B 16384
#define ATT_SMEM (16384 + 2 * ATT_STG_B)   // 49152

__global__ __launch_bounds__(256, 2) void attn_kernel(const float* __restrict__ gm)
{
    extern __shared__ __align__(16) char smem[];
    const uint32_t sb = s2u(smem);
    const int tid  = threadIdx.x;
    const int lane = tid & 31;
    const int w    = tid >> 5;
    const int h    = blockIdx.x;
    const int q0   = blockIdx.y * 128;
    const int b    = blockIdx.z;
    const int bh   = b * NHEAD + h;

    const __half* Qh = g_oqh + ((size_t)bh * SEQ + q0) * DHEAD;
    const __half* Kh = g_okh + (size_t)bh * SEQ * DHEAD;
    const __half* Vh = g_ovh + (size_t)bh * SEQ * DHEAD;

#pragma unroll
    for (int i = 0; i < 4; i++) {
        const int c = tid + i * 256;      // 0..1023
        const int r = c >> 3, off = c & 7;
        cp16(sb + ATT_Q + swz((uint32_t)r * 128 + off * 16),
             Qh + (size_t)r * DHEAD + off * 8);
    }
    auto load_stage = [&](int kt, int s) {
        const int k0 = kt * 64;
        const uint32_t base = sb + ATT_STG0 + (uint32_t)s * ATT_STG_B;
#pragma unroll
        for (int i = 0; i < 2; i++) {
            const int c = tid + i * 256;  // 0..511
            const int r = c >> 3, off = c & 7;
            const uint32_t d = swz((uint32_t)r * 128 + off * 16);
            const size_t g = (size_t)(k0 + r) * DHEAD + off * 8;
            cp16(base + d,        Kh + g);
            cp16(base + 8192 + d, Vh + g);
        }
    };
    load_stage(0, 0);
    asm volatile("cp.async.commit_group;" ::: "memory");
    load_stage(1, 1);
    asm volatile("cp.async.commit_group;" ::: "memory");
    asm volatile("cp.async.wait_group 1;" ::: "memory");
    __syncthreads();

    const int l8 = lane & 7, lg = lane >> 3;
    const int a_row_off = ((lg & 1) ? 8 : 0) + l8;
    const int a_col_off = (lg & 2) ? 8 : 0;
    const int b_row_off = ((lg >> 1) ? 8 : 0) + l8;
    const int b_col_off = (lg & 1) ? 8 : 0;

    uint32_t qfh[4][4];
    const uint32_t qrowbyte = (uint32_t)(w * 16 + a_row_off) * 128;
#pragma unroll
    for (int ks = 0; ks < 4; ks++)
        ldm_x4(qfh[ks], sb + ATT_Q + swz(qrowbyte + (ks * 16 + a_col_off) * 2));

    float accv[8][4];
#pragma unroll
    for (int i = 0; i < 8; i++)
#pragma unroll
        for (int j = 0; j < 4; j++) accv[i][j] = 0.0f;
    float m0 = -INFINITY, m1 = -INFINITY, l0 = 0.0f, l1 = 0.0f;

    const int r0 = lane >> 2;
    const int qrow0 = q0 + w * 16 + r0;
    const float* gmRow0 = gm + ((size_t)b * SEQ + qrow0) * SEQ;
    const float* gmRow1 = gmRow0 + 8 * SEQ;
    const int colq = (lane & 3) * 2;

    for (int kt = 0; kt < SEQ / 64; kt++) {
        const int st = kt & 1;
        const uint32_t stg = sb + ATT_STG0 + (uint32_t)st * ATT_STG_B;

        float s[8][4];
#pragma unroll
        for (int i = 0; i < 8; i++)
#pragma unroll
            for (int j = 0; j < 4; j++) s[i][j] = 0.0f;
#pragma unroll
        for (int ks = 0; ks < 4; ks++) {
#pragma unroll
            for (int g16 = 0; g16 < 4; g16++) {
                const int row = g16 * 16 + b_row_off;
                const int col = ks * 16 + b_col_off;
                uint32_t kh4[4];
                ldm_x4(kh4, stg + swz((uint32_t)row * 128 + col * 2));
                uint32_t bh0[2] = {kh4[0], kh4[1]}, bh1[2] = {kh4[2], kh4[3]};
                mma_f16(s[g16 * 2],     qfh[ks], bh0);
                mma_f16(s[g16 * 2 + 1], qfh[ks], bh1);
            }
        }

        float rm0 = -INFINITY, rm1 = -INFINITY;
#pragma unroll
        for (int nt = 0; nt < 8; nt++) {
            rm0 = fmaxf(rm0, fmaxf(s[nt][0], s[nt][1]));
            rm1 = fmaxf(rm1, fmaxf(s[nt][2], s[nt][3]));
        }
        rm0 = fmaxf(rm0, __shfl_xor_sync(0xffffffffu, rm0, 1));
        rm0 = fmaxf(rm0, __shfl_xor_sync(0xffffffffu, rm0, 2));
        rm1 = fmaxf(rm1, __shfl_xor_sync(0xffffffffu, rm1, 1));
        rm1 = fmaxf(rm1, __shfl_xor_sync(0xffffffffu, rm1, 2));
        const float m0n = fmaxf(m0, rm0);
        const float m1n = fmaxf(m1, rm1);
        const float c0 = ex2(m0 - m0n);
        const float c1 = ex2(m1 - m1n);
        l0 *= c0; l1 *= c1;
        m0 = m0n; m1 = m1n;
#pragma unroll
        for (int nt = 0; nt < 8; nt++) {
            accv[nt][0] *= c0; accv[nt][1] *= c0;
            accv[nt][2] *= c1; accv[nt][3] *= c1;
        }

        uint32_t aP[4][4];
        const int kbase = kt * 64 + colq;
#pragma unroll
        for (int nt = 0; nt < 8; nt++) {
            const int kc = kbase + nt * 8;
            const float2 g0 = *(const float2*)(gmRow0 + kc);
            const float2 g1 = *(const float2*)(gmRow1 + kc);
            const float p00 = ex2(s[nt][0] - m0);
            const float p01 = ex2(s[nt][1] - m0);
            const float p10 = ex2(s[nt][2] - m1);
            const float p11 = ex2(s[nt][3] - m1);
            l0 += (g0.x >= 0.0f ? p00 : 0.0f) + (g0.y >= 0.0f ? p01 : 0.0f);
            l1 += (g1.x >= 0.0f ? p10 : 0.0f) + (g1.y >= 0.0f ? p11 : 0.0f);
            const int ks = nt >> 1, half = (nt & 1) * 2;
            aP[ks][half + 0] = pack_h2(p00 * fmaxf(g0.x, 0.0f), p01 * fmaxf(g0.y, 0.0f));
            aP[ks][half + 1] = pack_h2(p10 * fmaxf(g1.x, 0.0f), p11 * fmaxf(g1.y, 0.0f));
        }

#pragma unroll
        for (int ks = 0; ks < 4; ks++) {
#pragma unroll
            for (int ng = 0; ng < 4; ng++) {
                const int row = ks * 16 + ((lg & 1) ? 8 : 0) + l8;
                const int col = ng * 16 + ((lg >> 1) ? 8 : 0);
                uint32_t vh4[4];
                ldm_x4_t(vh4, stg + 8192 + swz((uint32_t)row * 128 + col * 2));
                uint32_t bh0[2] = {vh4[0], vh4[1]}, bh1[2] = {vh4[2], vh4[3]};
                mma_f16(accv[ng * 2],     aP[ks], bh0);
                mma_f16(accv[ng * 2 + 1], aP[ks], bh1);
            }
        }

        __syncthreads();
        if (kt + 2 < SEQ / 64) load_stage(kt + 2, st);
        asm volatile("cp.async.commit_group;" ::: "memory");
        if (kt + 1 < SEQ / 64) {
            asm volatile("cp.async.wait_group 1;" ::: "memory");
            __syncthreads();
        }
    }

    l0 += __shfl_xor_sync(0xffffffffu, l0, 1);
    l0 += __shfl_xor_sync(0xffffffffu, l0, 2);
    l1 += __shfl_xor_sync(0xffffffffu, l1, 1);
    l1 += __shfl_xor_sync(0xffffffffu, l1, 2);
    const float inv0 = 1.0f / l0, inv1 = 1.0f / l1;

    const size_t tok0 = (size_t)b * SEQ + qrow0;
    __half* ch0 = g_ch + tok0 * DMODEL + h * DHEAD + colq;
#pragma unroll
    for (int nt = 0; nt < 8; nt++) {
        *(uint32_t*)(ch0 + nt * 8) = pack_h2(accv[nt][0] * inv0, accv[nt][1] * inv0);
        *(uint32_t*)(ch0 + 8 * DMODEL + nt * 8) =
            pack_h2(accv[nt][2] * inv1, accv[nt][3] * inv1);
    }
}

// ---------------------------------------------------------------------------
extern "C" void kernel_launch(void* const* d_in, const int* in_sizes, int n_in,
                              void* d_out, int out_size)
{
    (void)in_sizes; (void)n_in; (void)out_size;
    const float* query = (const float*)d_in[0];
    const float* key_  = (const float*)d_in[1];
    const float* value = (const float*)d_in[2];
    const int*   mask  = (const int*)  d_in[3];
    const float* group = (const float*)d_in[4];
    const float* bq = (const float*)d_in[6];
    const float* bk = (const float*)d_in[8];
    const float* bv = (const float*)d_in[10];
    const float* bo = (const float*)d_in[12];
    float* out = (float*)d_out;

    float* gmp;
    cudaGetSymbolAddress((void**)&gmp, g_gm);

    cudaFuncSetAttribute(gemm_qkv_kernel, cudaFuncAttributeMaxDynamicSharedMemorySize,
                         GEMM_SMEM);
    cudaFuncSetAttribute(gemm_out_kernel, cudaFuncAttributeMaxDynamicSharedMemorySize,
                         GEMM_SMEM);
    cudaFuncSetAttribute(attn_kernel, cudaFuncAttributeMaxDynamicSharedMemorySize,
                         ATT_SMEM);

    // one cvt launch: y = 7 sub-jobs (3 activations + 4 weights); x sized for
    // the larger (activation) job, weight blocks early-exit.
    cvt_kernel<<<dim3(NTOK * (DMODEL / 8) / 256, 7), 256>>>(
        query, key_, value,
        (const float*)d_in[5], (const float*)d_in[7],
        (const float*)d_in[9], (const float*)d_in[11]);
    prep_gm_kernel<<<BATCH * SEQ * SEQ / 4 / 256, 256>>>(mask, group, gmp);

    const float QSCALE = 0.125f * 1.44269504088896f;  // 1/sqrt(DK) * log2(e)
    gemm_qkv_kernel<<<dim3(DMODEL / BN, NTOK / BM, 3), GEMM_THREADS, GEMM_SMEM>>>(
        bq, bk, bv, QSCALE);

    attn_kernel<<<dim3(NHEAD, SEQ / 128, BATCH), 256, ATT_SMEM>>>(gmp);

    gemm_out_kernel<<<dim3(DMODEL / BN, NTOK / BM), GEMM_THREADS, GEMM_SMEM>>>(bo, out);
}

// round 12
// speedup vs baseline: 2.0952x; 1.0237x over previous
#include <cuda_runtime.h>
#include <cuda_fp16.h>
#include <math.h>
#include <stdint.h>

#define BATCH  4
#define SEQ    1024
#define DMODEL 1024
#define NHEAD  16
#define DHEAD  64
#define NTOK   (BATCH * SEQ)

// ---------------- scratch (device globals; no runtime alloc) ----------------
__device__ __half g_qa[NTOK * DMODEL], g_ka[NTOK * DMODEL], g_va[NTOK * DMODEL];
__device__ __half g_wq[DMODEL * DMODEL], g_wk[DMODEL * DMODEL];
__device__ __half g_wv[DMODEL * DMODEL], g_wo[DMODEL * DMODEL];
// projected Q/K/V, fp16, [b,h,s,64] layout (Q pre-scaled by .125*log2e)
__device__ __half g_oqh[NTOK * DMODEL];
__device__ __half g_okh[NTOK * DMODEL];
__device__ __half g_ovh[NTOK * DMODEL];
// attention context, fp16, row-major [tok][1024]
__device__ __half g_ch[NTOK * DMODEL];
// fused mask*group as fp16: allowed ? group : -1
__device__ __half g_gm[BATCH * SEQ * SEQ];

// ---------------------------------------------------------------------------
// shared PTX helpers
// ---------------------------------------------------------------------------
__device__ __forceinline__ uint32_t s2u(const void* p) {
    uint32_t a;
    asm("{ .reg .u64 t; cvta.to.shared.u64 t, %1; cvt.u32.u64 %0, t; }"
        : "=r"(a) : "l"(p));
    return a;
}
__device__ __forceinline__ void cp16(uint32_t dst, const void* src) {
    asm volatile("cp.async.cg.shared.global [%0], [%1], 16;" :: "r"(dst), "l"(src));
}
__device__ __forceinline__ void ldm_x4(uint32_t* r, uint32_t addr) {
    asm volatile("ldmatrix.sync.aligned.m8n8.x4.shared.b16 {%0,%1,%2,%3}, [%4];"
                 : "=r"(r[0]), "=r"(r[1]), "=r"(r[2]), "=r"(r[3]) : "r"(addr));
}
__device__ __forceinline__ void ldm_x4_t(uint32_t* r, uint32_t addr) {
    asm volatile("ldmatrix.sync.aligned.m8n8.x4.trans.shared.b16 {%0,%1,%2,%3}, [%4];"
                 : "=r"(r[0]), "=r"(r[1]), "=r"(r[2]), "=r"(r[3]) : "r"(addr));
}
__device__ __forceinline__ void mma_f16(float* c, const uint32_t* a,
                                        const uint32_t* b) {
    asm volatile(
        "mma.sync.aligned.m16n8k16.row.col.f32.f16.f16.f32 "
        "{%0,%1,%2,%3}, {%4,%5,%6,%7}, {%8,%9}, {%0,%1,%2,%3};"
        : "+f"(c[0]), "+f"(c[1]), "+f"(c[2]), "+f"(c[3])
        : "r"(a[0]), "r"(a[1]), "r"(a[2]), "r"(a[3]), "r"(b[0]), "r"(b[1]));
}
__device__ __forceinline__ uint32_t swz(uint32_t byte) {
    return byte ^ ((byte >> 3) & 0x70);
}
__device__ __forceinline__ uint32_t pack_h2(float x, float y) {
    uint32_t r;
    asm("cvt.rn.f16x2.f32 %0, %1, %2;" : "=r"(r) : "f"(y), "f"(x));
    return r;
}
__device__ __forceinline__ uint32_t ex2_h2(uint32_t d) {
    uint32_t r;
    asm("ex2.approx.f16x2 %0, %1;" : "=r"(r) : "r"(d));
    return r;
}
__device__ __forceinline__ float ex2(float x) {
    float r;
    asm("ex2.approx.f32 %0, %1;" : "=f"(r) : "f"(x));
    return r;
}

// ---------------------------------------------------------------------------
// conversions (fp32 -> fp16, plain)
// z=0..2: query/key/value activations; z=3..6: Wq/Wk/Wv/Wo
// ---------------------------------------------------------------------------
__global__ __launch_bounds__(256) void cvt_kernel(
    const float* __restrict__ s0, const float* __restrict__ s1,
    const float* __restrict__ s2, const float* __restrict__ s3,
    const float* __restrict__ s4, const float* __restrict__ s5,
    const float* __restrict__ s6)
{
    const int z = blockIdx.y;
    const int n8 = (z < 3) ? NTOK * (DMODEL / 8) : DMODEL * (DMODEL / 8);
    const int t = blockIdx.x * 256 + threadIdx.x;
    if (t >= n8) return;
    const float* src;
    __half* dst;
    switch (z) {
        case 0: src = s0; dst = g_qa; break;
        case 1: src = s1; dst = g_ka; break;
        case 2: src = s2; dst = g_va; break;
        case 3: src = s3; dst = g_wq; break;
        case 4: src = s4; dst = g_wk; break;
        case 5: src = s5; dst = g_wv; break;
        default: src = s6; dst = g_wo; break;
    }
    const int idx = t * 8;
    const float4 a = *(const float4*)(src + idx);
    const float4 b = *(const float4*)(src + idx + 4);
    uint4 o;
    o.x = pack_h2(a.x, a.y);
    o.y = pack_h2(a.z, a.w);
    o.z = pack_h2(b.x, b.y);
    o.w = pack_h2(b.z, b.w);
    *(uint4*)(dst + idx) = o;
}

// gm(fp16) = (mask || q==k) ? group : -1
__global__ __launch_bounds__(256) void prep_gm_kernel(
    const int* __restrict__ mask, const float* __restrict__ group,
    __half* __restrict__ gm)
{
    const int t = blockIdx.x * 256 + threadIdx.x;
    if (t >= BATCH * SEQ * SEQ / 8) return;
    const int i = t * 8;
    const int q = (i >> 10) & 1023;
    const int k = i & 1023;
    const int4 mk0 = *(const int4*)(mask + i);
    const int4 mk1 = *(const int4*)(mask + i + 4);
    const float4 g0 = *(const float4*)(group + i);
    const float4 g1 = *(const float4*)(group + i + 4);
    const float v[8] = {
        (mk0.x || q == k + 0) ? g0.x : -1.0f,
        (mk0.y || q == k + 1) ? g0.y : -1.0f,
        (mk0.z || q == k + 2) ? g0.z : -1.0f,
        (mk0.w || q == k + 3) ? g0.w : -1.0f,
        (mk1.x || q == k + 4) ? g1.x : -1.0f,
        (mk1.y || q == k + 5) ? g1.y : -1.0f,
        (mk1.z || q == k + 6) ? g1.z : -1.0f,
        (mk1.w || q == k + 7) ? g1.w : -1.0f};
    uint4 o;
    o.x = pack_h2(v[0], v[1]);
    o.y = pack_h2(v[2], v[3]);
    o.z = pack_h2(v[4], v[5]);
    o.w = pack_h2(v[6], v[7]);
    *(uint4*)(gm + i) = o;
}

// ---------------------------------------------------------------------------
// fp16 GEMM: out[r,c] = sum_k A[r,k] * W[c,k] + bias[c]
// CTA tile 128x256, BK=64, 3 stages, 512 threads (16 warps, 32x64 warp tile).
// ---------------------------------------------------------------------------
#define GEMM_THREADS 512
#define BM 128
#define BN 256
#define BK 64
#define STAGES 3
#define KTILES (DMODEL / BK)          // 16
#define PAD_B 144
#define TILE_AB (128 * PAD_B)         // 18432
#define TILE_BB (256 * PAD_B)         // 36864
#define OFF_BH  TILE_AB
#define STAGE_B (TILE_AB + TILE_BB)       // 55296
#define GEMM_SMEM (STAGES * STAGE_B)      // 165888

__device__ __forceinline__ void gemm_body(
    const __half* __restrict__ aH, const __half* __restrict__ bH,
    const float* __restrict__ bias, float* __restrict__ outF,
    __half* __restrict__ outH,
    int mode, float oscale, int brow, int bcol, char* smem)
{
    const uint32_t sb = s2u(smem);
    const int tid  = threadIdx.x;
    const int lane = tid & 31;
    const int wid  = tid >> 5;
    const int warpM = wid >> 2;
    const int warpN = wid & 3;

    float acc[2][8][4];
#pragma unroll
    for (int i = 0; i < 2; i++)
#pragma unroll
        for (int j = 0; j < 8; j++)
#pragma unroll
            for (int k = 0; k < 4; k++) acc[i][j][k] = 0.0f;

    auto load_stage = [&](int kb, int s) {
        const int k0 = kb * BK;
        const uint32_t base = sb + (uint32_t)s * STAGE_B;
#pragma unroll
        for (int i = 0; i < 2; i++) {
            const int c = tid + i * GEMM_THREADS;
            const int r = c >> 3;
            const int q = c & 7;
            cp16(base + (uint32_t)r * PAD_B + q * 16,
                 aH + (size_t)(brow + r) * DMODEL + k0 + q * 8);
        }
#pragma unroll
        for (int i = 0; i < 4; i++) {
            const int c = tid + i * GEMM_THREADS;
            const int r = c >> 3;
            const int q = c & 7;
            cp16(base + OFF_BH + (uint32_t)r * PAD_B + q * 16,
                 bH + (size_t)(bcol + r) * DMODEL + k0 + q * 8);
        }
        asm volatile("cp.async.commit_group;" ::: "memory");
    };

    const int l8 = lane & 7, lg = lane >> 3;
    const int a_row_off = ((lg & 1) ? 8 : 0) + l8;
    const int a_col_off = (lg & 2) ? 8 : 0;
    const int b_row_off = ((lg >> 1) ? 8 : 0) + l8;
    const int b_col_off = (lg & 1) ? 8 : 0;

    load_stage(0, 0);
    load_stage(1, 1);
    asm volatile("cp.async.wait_group 1;" ::: "memory");
    __syncthreads();

    for (int kb = 0; kb < KTILES; kb++) {
        const uint32_t stg = sb + (uint32_t)(kb % STAGES) * STAGE_B;
#pragma unroll
        for (int ks = 0; ks < 4; ks++) {
            uint32_t ah[2][4];
#pragma unroll
            for (int mt = 0; mt < 2; mt++) {
                const int row = warpM * 32 + mt * 16 + a_row_off;
                const int col = ks * 16 + a_col_off;
                ldm_x4(ah[mt], stg + (uint32_t)row * PAD_B + col * 2);
            }
#pragma unroll
            for (int pt = 0; pt < 4; pt++) {
                const int n   = warpN * 64 + pt * 16 + b_row_off;
                const int col = ks * 16 + b_col_off;
                uint32_t th[4];
                ldm_x4(th, stg + OFF_BH + (uint32_t)n * PAD_B + col * 2);
                uint32_t bh0[2] = {th[0], th[1]}, bh1[2] = {th[2], th[3]};
#pragma unroll
                for (int mt = 0; mt < 2; mt++) {
                    mma_f16(acc[mt][pt * 2],     ah[mt], bh0);
                    mma_f16(acc[mt][pt * 2 + 1], ah[mt], bh1);
                }
            }
        }
        __syncthreads();
        if (kb + 2 < KTILES) load_stage(kb + 2, (kb + 2) % STAGES);
        else asm volatile("cp.async.commit_group;" ::: "memory");
        if (kb + 1 < KTILES) {
            asm volatile("cp.async.wait_group 1;" ::: "memory");
            __syncthreads();
        }
    }

#pragma unroll
    for (int mt = 0; mt < 2; mt++) {
        const int row = brow + warpM * 32 + mt * 16 + (lane >> 2);
#pragma unroll
        for (int nt = 0; nt < 8; nt++) {
            const int col = bcol + warpN * 64 + (nt >> 1) * 16 + (nt & 1) * 8
                          + (lane & 3) * 2;
            const float b0 = bias[col], b1 = bias[col + 1];
            const float v00 = acc[mt][nt][0] + b0, v01 = acc[mt][nt][1] + b1;
            const float v10 = acc[mt][nt][2] + b0, v11 = acc[mt][nt][3] + b1;
            if (mode == 0) {
                *(float2*)(outF + (size_t)row * DMODEL + col) = make_float2(v00, v01);
                *(float2*)(outF + (size_t)(row + 8) * DMODEL + col) = make_float2(v10, v11);
            } else {
                const int h = col >> 6, dk = col & 63;
                const int bi = row >> 10, s = row & 1023;
                const size_t d0 = (((size_t)(bi * NHEAD + h)) * SEQ + s) * DHEAD + dk;
                *(uint32_t*)(outH + d0) = pack_h2(v00 * oscale, v01 * oscale);
                *(uint32_t*)(outH + d0 + 8 * DHEAD) = pack_h2(v10 * oscale, v11 * oscale);
            }
        }
    }
}

__global__ __launch_bounds__(GEMM_THREADS, 1) void gemm_qkv_kernel(
    const float* __restrict__ bq, const float* __restrict__ bk,
    const float* __restrict__ bv, float qscale)
{
    extern __shared__ __align__(16) char smem[];
    const int z = blockIdx.z;
    const __half *aH, *bH;
    __half *oH;
    const float* bias;
    float sc;
    if (z == 0)      { aH = g_qa; bH = g_wq; oH = g_oqh; bias = bq; sc = qscale; }
    else if (z == 1) { aH = g_ka; bH = g_wk; oH = g_okh; bias = bk; sc = 1.0f; }
    else             { aH = g_va; bH = g_wv; oH = g_ovh; bias = bv; sc = 1.0f; }
    gemm_body(aH, bH, bias, nullptr, oH, 1, sc,
              blockIdx.y * BM, blockIdx.x * BN, smem);
}

__global__ __launch_bounds__(GEMM_THREADS, 1) void gemm_out_kernel(
    const float* __restrict__ bo, float* __restrict__ out)
{
    extern __shared__ __align__(16) char smem[];
    gemm_body(g_ch, g_wo, bo, out, nullptr, 0, 1.0f,
              blockIdx.y * BM, blockIdx.x * BN, smem);
}

// ---------------------------------------------------------------------------
// Single-pass fp16 flash attention; softmax tail in f16x2 (ex2.approx.f16x2),
// gm in fp16. l kept in fp32. CTA = 128 q-rows x (b,h), 8 warps, 64-key tiles.
// ---------------------------------------------------------------------------
#define ATT_Q 0
#define ATT_STG0 16384
#define ATT_STG_B 16384
#define ATT_SMEM (16384 + 2 * ATT_STG_B)   // 49152

__global__ __launch_bounds__(256, 2) void attn_kernel(const __half* __restrict__ gm)
{
    extern __shared__ __align__(16) char smem[];
    const uint32_t sb = s2u(smem);
    const int tid  = threadIdx.x;
    const int lane = tid & 31;
    const int w    = tid >> 5;
    const int h    = blockIdx.x;
    const int q0   = blockIdx.y * 128;
    const int b    = blockIdx.z;
    const int bh   = b * NHEAD + h;

    const __half* Qh = g_oqh + ((size_t)bh * SEQ + q0) * DHEAD;
    const __half* Kh = g_okh + (size_t)bh * SEQ * DHEAD;
    const __half* Vh = g_ovh + (size_t)bh * SEQ * DHEAD;

#pragma unroll
    for (int i = 0; i < 4; i++) {
        const int c = tid + i * 256;
        const int r = c >> 3, off = c & 7;
        cp16(sb + ATT_Q + swz((uint32_t)r * 128 + off * 16),
             Qh + (size_t)r * DHEAD + off * 8);
    }
    auto load_stage = [&](int kt, int s) {
        const int k0 = kt * 64;
        const uint32_t base = sb + ATT_STG0 + (uint32_t)s * ATT_STG_B;
#pragma unroll
        for (int i = 0; i < 2; i++) {
            const int c = tid + i * 256;
            const int r = c >> 3, off = c & 7;
            const uint32_t d = swz((uint32_t)r * 128 + off * 16);
            const size_t g = (size_t)(k0 + r) * DHEAD + off * 8;
            cp16(base + d,        Kh + g);
            cp16(base + 8192 + d, Vh + g);
        }
    };
    load_stage(0, 0);
    asm volatile("cp.async.commit_group;" ::: "memory");
    load_stage(1, 1);
    asm volatile("cp.async.commit_group;" ::: "memory");
    asm volatile("cp.async.wait_group 1;" ::: "memory");
    __syncthreads();

    const int l8 = lane & 7, lg = lane >> 3;
    const int a_row_off = ((lg & 1) ? 8 : 0) + l8;
    const int a_col_off = (lg & 2) ? 8 : 0;
    const int b_row_off = ((lg >> 1) ? 8 : 0) + l8;
    const int b_col_off = (lg & 1) ? 8 : 0;

    uint32_t qfh[4][4];
    const uint32_t qrowbyte = (uint32_t)(w * 16 + a_row_off) * 128;
#pragma unroll
    for (int ks = 0; ks < 4; ks++)
        ldm_x4(qfh[ks], sb + ATT_Q + swz(qrowbyte + (ks * 16 + a_col_off) * 2));

    float accv[8][4];
#pragma unroll
    for (int i = 0; i < 8; i++)
#pragma unroll
        for (int j = 0; j < 4; j++) accv[i][j] = 0.0f;
    float m0 = -INFINITY, m1 = -INFINITY, l0 = 0.0f, l1 = 0.0f;

    const int r0 = lane >> 2;
    const int qrow0 = q0 + w * 16 + r0;
    const __half* gmRow0 = gm + ((size_t)b * SEQ + qrow0) * SEQ;
    const __half* gmRow1 = gmRow0 + 8 * SEQ;
    const int colq = (lane & 3) * 2;
    const __half2 zero2 = __float2half2_rn(0.0f);

    for (int kt = 0; kt < SEQ / 64; kt++) {
        const int st = kt & 1;
        const uint32_t stg = sb + ATT_STG0 + (uint32_t)st * ATT_STG_B;

        // ---- S = Qh Kh^T ----
        float s[8][4];
#pragma unroll
        for (int i = 0; i < 8; i++)
#pragma unroll
            for (int j = 0; j < 4; j++) s[i][j] = 0.0f;
#pragma unroll
        for (int ks = 0; ks < 4; ks++) {
#pragma unroll
            for (int g16 = 0; g16 < 4; g16++) {
                const int row = g16 * 16 + b_row_off;
                const int col = ks * 16 + b_col_off;
                uint32_t kh4[4];
                ldm_x4(kh4, stg + swz((uint32_t)row * 128 + col * 2));
                uint32_t bh0[2] = {kh4[0], kh4[1]}, bh1[2] = {kh4[2], kh4[3]};
                mma_f16(s[g16 * 2],     qfh[ks], bh0);
                mma_f16(s[g16 * 2 + 1], qfh[ks], bh1);
            }
        }

        // ---- online softmax (log2 domain, f16x2 tail) ----
        float rm0 = -INFINITY, rm1 = -INFINITY;
#pragma unroll
        for (int nt = 0; nt < 8; nt++) {
            rm0 = fmaxf(rm0, fmaxf(s[nt][0], s[nt][1]));
            rm1 = fmaxf(rm1, fmaxf(s[nt][2], s[nt][3]));
        }
        rm0 = fmaxf(rm0, __shfl_xor_sync(0xffffffffu, rm0, 1));
        rm0 = fmaxf(rm0, __shfl_xor_sync(0xffffffffu, rm0, 2));
        rm1 = fmaxf(rm1, __shfl_xor_sync(0xffffffffu, rm1, 1));
        rm1 = fmaxf(rm1, __shfl_xor_sync(0xffffffffu, rm1, 2));
        const float m0n = fmaxf(m0, rm0);
        const float m1n = fmaxf(m1, rm1);
        const float c0 = ex2(m0 - m0n);
        const float c1 = ex2(m1 - m1n);
        l0 *= c0; l1 *= c1;
        m0 = m0n; m1 = m1n;
#pragma unroll
        for (int nt = 0; nt < 8; nt++) {
            accv[nt][0] *= c0; accv[nt][1] *= c0;
            accv[nt][2] *= c1; accv[nt][3] *= c1;
        }

        uint32_t aP[4][4];
        float lacc0 = 0.0f, lacc1 = 0.0f;
        const int kbase = kt * 64 + colq;
#pragma unroll
        for (int nt = 0; nt < 8; nt++) {
            const int kc = kbase + nt * 8;
            const __half2 gs0 = *(const __half2*)(gmRow0 + kc);
            const __half2 gs1 = *(const __half2*)(gmRow1 + kc);
            const uint32_t p0u = ex2_h2(pack_h2(s[nt][0] - m0, s[nt][1] - m0));
            const uint32_t p1u = ex2_h2(pack_h2(s[nt][2] - m1, s[nt][3] - m1));
            const __half2 p0 = *(const __half2*)&p0u;
            const __half2 p1 = *(const __half2*)&p1u;
            const __half2 w0 = __hmax2(gs0, zero2);
            const __half2 w1 = __hmax2(gs1, zero2);
            const __half2 k0 = __hge2(gs0, zero2);   // 1.0 where allowed
            const __half2 k1 = __hge2(gs1, zero2);
            const __half2 a0 = __hmul2(p0, w0);
            const __half2 a1 = __hmul2(p1, w1);
            const int ks = nt >> 1, hf = (nt & 1) * 2;
            aP[ks][hf + 0] = *(const uint32_t*)&a0;
            aP[ks][hf + 1] = *(const uint32_t*)&a1;
            const float2 f0 = __half22float2(__hmul2(p0, k0));
            const float2 f1 = __half22float2(__hmul2(p1, k1));
            lacc0 += f0.x + f0.y;
            lacc1 += f1.x + f1.y;
        }
        l0 += lacc0;
        l1 += lacc1;

        // ---- acc += P Vh ----
#pragma unroll
        for (int ks = 0; ks < 4; ks++) {
#pragma unroll
            for (int ng = 0; ng < 4; ng++) {
                const int row = ks * 16 + ((lg & 1) ? 8 : 0) + l8;
                const int col = ng * 16 + ((lg >> 1) ? 8 : 0);
                uint32_t vh4[4];
                ldm_x4_t(vh4, stg + 8192 + swz((uint32_t)row * 128 + col * 2));
                uint32_t bh0[2] = {vh4[0], vh4[1]}, bh1[2] = {vh4[2], vh4[3]};
                mma_f16(accv[ng * 2],     aP[ks], bh0);
                mma_f16(accv[ng * 2 + 1], aP[ks], bh1);
            }
        }

        __syncthreads();
        if (kt + 2 < SEQ / 64) load_stage(kt + 2, st);
        asm volatile("cp.async.commit_group;" ::: "memory");
        if (kt + 1 < SEQ / 64) {
            asm volatile("cp.async.wait_group 1;" ::: "memory");
            __syncthreads();
        }
    }

    l0 += __shfl_xor_sync(0xffffffffu, l0, 1);
    l0 += __shfl_xor_sync(0xffffffffu, l0, 2);
    l1 += __shfl_xor_sync(0xffffffffu, l1, 1);
    l1 += __shfl_xor_sync(0xffffffffu, l1, 2);
    const float inv0 = 1.0f / l0, inv1 = 1.0f / l1;

    const size_t tok0 = (size_t)b * SEQ + qrow0;
    __half* ch0 = g_ch + tok0 * DMODEL + h * DHEAD + colq;
#pragma unroll
    for (int nt = 0; nt < 8; nt++) {
        *(uint32_t*)(ch0 + nt * 8) = pack_h2(accv[nt][0] * inv0, accv[nt][1] * inv0);
        *(uint32_t*)(ch0 + 8 * DMODEL + nt * 8) =
            pack_h2(accv[nt][2] * inv1, accv[nt][3] * inv1);
    }
}

// ---------------------------------------------------------------------------
extern "C" void kernel_launch(void* const* d_in, const int* in_sizes, int n_in,
                              void* d_out, int out_size)
{
    (void)in_sizes; (void)n_in; (void)out_size;
    const float* query = (const float*)d_in[0];
    const float* key_  = (const float*)d_in[1];
    const float* value = (const float*)d_in[2];
    const int*   mask  = (const int*)  d_in[3];
    const float* group = (const float*)d_in[4];
    const float* bq = (const float*)d_in[6];
    const float* bk = (const float*)d_in[8];
    const float* bv = (const float*)d_in[10];
    const float* bo = (const float*)d_in[12];
    float* out = (float*)d_out;

    __half* gmp;
    cudaGetSymbolAddress((void**)&gmp, g_gm);

    cudaFuncSetAttribute(gemm_qkv_kernel, cudaFuncAttributeMaxDynamicSharedMemorySize,
                         GEMM_SMEM);
    cudaFuncSetAttribute(gemm_out_kernel, cudaFuncAttributeMaxDynamicSharedMemorySize,
                         GEMM_SMEM);
    cudaFuncSetAttribute(attn_kernel, cudaFuncAttributeMaxDynamicSharedMemorySize,
                         ATT_SMEM);

    cvt_kernel<<<dim3(NTOK * (DMODEL / 8) / 256, 7), 256>>>(
        query, key_, value,
        (const float*)d_in[5], (const float*)d_in[7],
        (const float*)d_in[9], (const float*)d_in[11]);
    prep_gm_kernel<<<BATCH * SEQ * SEQ / 8 / 256, 256>>>(mask, group, gmp);

    const float QSCALE = 0.125f * 1.44269504088896f;  // 1/sqrt(DK) * log2(e)
    gemm_qkv_kernel<<<dim3(DMODEL / BN, NTOK / BM, 3), GEMM_THREADS, GEMM_SMEM>>>(
        bq, bk, bv, QSCALE);

    attn_kernel<<<dim3(NHEAD, SEQ / 128, BATCH), 256, ATT_SMEM>>>(gmp);

    gemm_out_kernel<<<dim3(DMODEL / BN, NTOK / BM), GEMM_THREADS, GEMM_SMEM>>>(bo, out);
}